// round 4
// baseline (speedup 1.0000x reference)
#include <cuda_runtime.h>
#include <cuda_fp16.h>
#include <cstdint>
#include <math.h>

#define S_  2048
#define D_  4096
#define H_  32
#define HD_ 128
#define FF_ 11008

// ---------------- scratch (no allocations allowed) ----------------
__device__ float g_q   [(size_t)S_ * D_];
__device__ float g_k   [(size_t)S_ * D_];
__device__ float g_v   [(size_t)S_ * D_];
__device__ float g_x2  [(size_t)S_ * D_];
__device__ float g_gate[(size_t)S_ * FF_];
__device__ float g_up  [(size_t)S_ * FF_];

// transposed + hi/lo split weights (fp16), layout [N, K] row-major
__device__ __half g_wqt_h[(size_t)D_ * D_];
__device__ __half g_wqt_l[(size_t)D_ * D_];
__device__ __half g_wkt_h[(size_t)D_ * D_];
__device__ __half g_wkt_l[(size_t)D_ * D_];
__device__ __half g_wvt_h[(size_t)D_ * D_];
__device__ __half g_wvt_l[(size_t)D_ * D_];
__device__ __half g_wot_h[(size_t)D_ * D_];
__device__ __half g_wot_l[(size_t)D_ * D_];
__device__ __half g_wgt_h[(size_t)FF_ * D_];
__device__ __half g_wgt_l[(size_t)FF_ * D_];
__device__ __half g_w1t_h[(size_t)FF_ * D_];
__device__ __half g_w1t_l[(size_t)FF_ * D_];
__device__ __half g_w2t_h[(size_t)D_ * FF_];
__device__ __half g_w2t_l[(size_t)D_ * FF_];

// activation hi/lo split scratch (reused sequentially)
__device__ __half g_a_h[(size_t)S_ * FF_];
__device__ __half g_a_l[(size_t)S_ * FF_];

// ---------------- asm helpers ----------------
__device__ __forceinline__ uint32_t smem_to_u32(const void* p) {
    uint32_t a;
    asm("{ .reg .u64 t; cvta.to.shared.u64 t, %1; cvt.u32.u64 %0, t; }" : "=r"(a) : "l"(p));
    return a;
}
__device__ __forceinline__ void cp16(uint32_t saddr, const void* gaddr) {
    asm volatile("cp.async.cg.shared.global [%0], [%1], 16;" :: "r"(saddr), "l"(gaddr));
}
#define CP_COMMIT() asm volatile("cp.async.commit_group;" ::: "memory")
#define CP_WAIT(n)  asm volatile("cp.async.wait_group %0;" :: "n"(n) : "memory")

#define LDSM_X4(r0, r1, r2, r3, addr) \
    asm volatile("ldmatrix.sync.aligned.m8n8.x4.shared.b16 {%0,%1,%2,%3}, [%4];" \
        : "=r"(r0), "=r"(r1), "=r"(r2), "=r"(r3) : "r"(addr))
#define LDSM_X4_T(r0, r1, r2, r3, addr) \
    asm volatile("ldmatrix.sync.aligned.m8n8.x4.trans.shared.b16 {%0,%1,%2,%3}, [%4];" \
        : "=r"(r0), "=r"(r1), "=r"(r2), "=r"(r3) : "r"(addr))

#define MMA16816(d, a, b) \
    asm volatile("mma.sync.aligned.m16n8k16.row.col.f32.f16.f16.f32 " \
        "{%0,%1,%2,%3}, {%4,%5,%6,%7}, {%8,%9}, {%0,%1,%2,%3};" \
        : "+f"((d)[0]), "+f"((d)[1]), "+f"((d)[2]), "+f"((d)[3]) \
        : "r"((a)[0]), "r"((a)[1]), "r"((a)[2]), "r"((a)[3]), "r"((b)[0]), "r"((b)[1]))
#define MMA4(d, a0, a1, a2, a3, b0, b1) \
    asm volatile("mma.sync.aligned.m16n8k16.row.col.f32.f16.f16.f32 " \
        "{%0,%1,%2,%3}, {%4,%5,%6,%7}, {%8,%9}, {%0,%1,%2,%3};" \
        : "+f"((d)[0]), "+f"((d)[1]), "+f"((d)[2]), "+f"((d)[3]) \
        : "r"(a0), "r"(a1), "r"(a2), "r"(a3), "r"(b0), "r"(b1))

__device__ __forceinline__ uint32_t packh(__half a, __half b) {
    return ((uint32_t)__half_as_ushort(b) << 16) | __half_as_ushort(a);
}
// 8 floats -> 16B hi chunk + 16B lo chunk
__device__ __forceinline__ void cvt8(const float* v, uint4& hv, uint4& lv) {
    uint32_t hh[4], ll[4];
    #pragma unroll
    for (int j = 0; j < 4; j++) {
        float a = v[2 * j], b = v[2 * j + 1];
        __half ha = __float2half_rn(a), hb = __float2half_rn(b);
        __half la = __float2half_rn(a - __half2float(ha));
        __half lb = __float2half_rn(b - __half2float(hb));
        hh[j] = packh(ha, hb); ll[j] = packh(la, lb);
    }
    hv = make_uint4(hh[0], hh[1], hh[2], hh[3]);
    lv = make_uint4(ll[0], ll[1], ll[2], ll[3]);
}

// ---------------- weight transpose + hi/lo split ----------------
__global__ __launch_bounds__(256) void wsplit_kernel(
    const float* __restrict__ W, __half* __restrict__ Wh,
    __half* __restrict__ Wl, int K, int N)
{
    __shared__ float t[32][33];
    int n0 = blockIdx.x * 32, k0 = blockIdx.y * 32;
    int tx = threadIdx.x, ty = threadIdx.y; // (32, 8)
    #pragma unroll
    for (int i = 0; i < 4; i++)
        t[ty + 8 * i][tx] = W[(size_t)(k0 + ty + 8 * i) * N + n0 + tx];
    __syncthreads();
    #pragma unroll
    for (int i = 0; i < 4; i++) {
        float v = t[tx][ty + 8 * i];
        __half hi = __float2half_rn(v);
        __half lo = __float2half_rn(v - __half2float(hi));
        size_t o = (size_t)(n0 + ty + 8 * i) * K + k0 + tx;
        Wh[o] = hi; Wl[o] = lo;
    }
}

// ---------------- HMMA GEMM v2: CTA 128x256, BK=64, 2-stage ----------------
#define STG_B 98304  // Ah 16K | Al 16K | Bh 32K | Bl 32K
#define HGEMM_SMEM (2 * STG_B)

template <bool RESID>
__global__ __launch_bounds__(256, 1) void hgemm(
    int M, int N, int K,
    const __half* __restrict__ Ah, const __half* __restrict__ Al,
    const __half* __restrict__ Bh, const __half* __restrict__ Bl,
    const float* __restrict__ Rsd, float* __restrict__ C)
{
    extern __shared__ __align__(1024) char smem[];
    const int tid  = threadIdx.x;
    const int wid  = tid >> 5;
    const int lane = tid & 31;
    const int m0 = blockIdx.x * 128;
    const int n0 = blockIdx.y * 256;
    const int nk = K >> 6;
    const uint32_t sbase = smem_to_u32(smem);

    const int wm = (wid & 1) * 64;
    const int wn = (wid >> 1) * 64;
    const int mat = lane >> 3, rin = lane & 7;

    const __half* Abase_h = Ah + (size_t)m0 * K;
    const __half* Abase_l = Al + (size_t)m0 * K;
    const __half* Bbase_h = Bh + (size_t)n0 * K;
    const __half* Bbase_l = Bl + (size_t)n0 * K;

    #define ISSUE(s, kt) do { \
        uint32_t sb_ = sbase + (s) * STG_B; \
        size_t kofs_ = (size_t)(kt) << 6; \
        _Pragma("unroll") \
        for (int t = 0; t < 4; t++) { \
            int c = tid + t * 256; \
            int row = c >> 3, cc = c & 7; \
            uint32_t so_ = sb_ + row * 128 + ((cc ^ (row & 7)) << 4); \
            size_t go_ = (size_t)row * K + kofs_ + cc * 8; \
            cp16(so_,         Abase_h + go_); \
            cp16(so_ + 16384, Abase_l + go_); \
        } \
        _Pragma("unroll") \
        for (int t = 0; t < 8; t++) { \
            int c = tid + t * 256; \
            int row = c >> 3, cc = c & 7; \
            uint32_t so_ = sb_ + 32768 + row * 128 + ((cc ^ (row & 7)) << 4); \
            size_t go_ = (size_t)row * K + kofs_ + cc * 8; \
            cp16(so_,         Bbase_h + go_); \
            cp16(so_ + 32768, Bbase_l + go_); \
        } \
    } while (0)

    float acc[4][8][4] = {};

    ISSUE(0, 0); CP_COMMIT();

    for (int i = 0; i < nk; i++) {
        if (i + 1 < nk) { ISSUE((i + 1) & 1, i + 1); CP_COMMIT(); CP_WAIT(1); }
        else            { CP_WAIT(0); }
        __syncthreads();

        uint32_t stg = sbase + (i & 1) * STG_B;
        #pragma unroll
        for (int ks = 0; ks < 4; ks++) {
            int ks2 = ks << 1;
            uint32_t fb_h[8][2], fb_l[8][2];
            #pragma unroll
            for (int p = 0; p < 4; p++) {
                int n = wn + p * 16 + ((mat >> 1) << 3) + rin;
                uint32_t bd = stg + 32768 + n * 128 + (((ks2 + (mat & 1)) ^ (n & 7)) << 4);
                uint32_t r0, r1, r2, r3;
                LDSM_X4(r0, r1, r2, r3, bd);
                fb_h[p * 2][0] = r0; fb_h[p * 2][1] = r1;
                fb_h[p * 2 + 1][0] = r2; fb_h[p * 2 + 1][1] = r3;
                LDSM_X4(r0, r1, r2, r3, bd + 32768);
                fb_l[p * 2][0] = r0; fb_l[p * 2][1] = r1;
                fb_l[p * 2 + 1][0] = r2; fb_l[p * 2 + 1][1] = r3;
            }
            #pragma unroll
            for (int mt = 0; mt < 4; mt++) {
                int m = wm + mt * 16 + ((mat & 1) << 3) + rin;
                uint32_t ad = stg + m * 128 + (((ks2 + (mat >> 1)) ^ (m & 7)) << 4);
                uint32_t ah[4], al[4];
                LDSM_X4(ah[0], ah[1], ah[2], ah[3], ad);
                LDSM_X4(al[0], al[1], al[2], al[3], ad + 16384);
                #pragma unroll
                for (int nt = 0; nt < 8; nt++) {
                    MMA16816(acc[mt][nt], ah, fb_h[nt]);
                    MMA16816(acc[mt][nt], ah, fb_l[nt]);
                    MMA16816(acc[mt][nt], al, fb_h[nt]);
                }
            }
        }
        __syncthreads();
    }
    #undef ISSUE

    int qr = lane >> 2, qc = (lane & 3) << 1;
    #pragma unroll
    for (int mt = 0; mt < 4; mt++) {
        #pragma unroll
        for (int nt = 0; nt < 8; nt++) {
            int r0 = m0 + wm + mt * 16 + qr;
            int cc = n0 + wn + nt * 8 + qc;
            float2 v0 = make_float2(acc[mt][nt][0], acc[mt][nt][1]);
            float2 v1 = make_float2(acc[mt][nt][2], acc[mt][nt][3]);
            if (RESID) {
                float2 a = *(const float2*)(Rsd + (size_t)r0 * N + cc);
                float2 b = *(const float2*)(Rsd + (size_t)(r0 + 8) * N + cc);
                v0.x += a.x; v0.y += a.y; v1.x += b.x; v1.y += b.y;
            }
            *(float2*)(C + (size_t)r0 * N + cc)       = v0;
            *(float2*)(C + (size_t)(r0 + 8) * N + cc) = v1;
        }
    }
}

// ---------------- RMSNorm with fused fp16 hi/lo split output ----------------
__global__ __launch_bounds__(256) void rmsnorm_split_kernel(
    const float* __restrict__ x, const float* __restrict__ w,
    __half* __restrict__ oh, __half* __restrict__ ol)
{
    int row = blockIdx.x;
    const float4* xr = (const float4*)(x + (size_t)row * D_);
    float ss = 0.f;
    #pragma unroll 4
    for (int i = threadIdx.x; i < D_ / 4; i += 256) {
        float4 v = xr[i];
        ss += v.x * v.x + v.y * v.y + v.z * v.z + v.w * v.w;
    }
    __shared__ float red[8];
    #pragma unroll
    for (int o = 16; o; o >>= 1) ss += __shfl_xor_sync(0xffffffffu, ss, o);
    if ((threadIdx.x & 31) == 0) red[threadIdx.x >> 5] = ss;
    __syncthreads();
    if (threadIdx.x == 0) {
        float t = 0.f;
        #pragma unroll
        for (int i = 0; i < 8; i++) t += red[i];
        red[0] = rsqrtf(t / (float)D_ + 1e-5f);
    }
    __syncthreads();
    float inv = red[0];
    const float4* wr = (const float4*)w;
    for (int i = threadIdx.x; i < D_ / 8; i += 256) {
        float vv[8];
        float4 a = xr[2 * i], b = xr[2 * i + 1];
        float4 wa = wr[2 * i], wb = wr[2 * i + 1];
        vv[0] = a.x * inv * wa.x; vv[1] = a.y * inv * wa.y;
        vv[2] = a.z * inv * wa.z; vv[3] = a.w * inv * wa.w;
        vv[4] = b.x * inv * wb.x; vv[5] = b.y * inv * wb.y;
        vv[6] = b.z * inv * wb.z; vv[7] = b.w * inv * wb.w;
        uint4 hv, lv;
        cvt8(vv, hv, lv);
        ((uint4*)(oh + (size_t)row * D_))[i] = hv;
        ((uint4*)(ol + (size_t)row * D_))[i] = lv;
    }
}

// ---------------- RoPE (q and k in place, fp32) ----------------
__global__ void rope_kernel(float* __restrict__ q, float* __restrict__ k)
{
    int s = blockIdx.x;
    int j = threadIdx.x;   // 0..63 pair index
    float inv = (float)exp((double)j * -0.14391156831212787);
    float ang = (float)s * inv;
    float sn, cs;
    sincosf(ang, &sn, &cs);
    #pragma unroll 4
    for (int h = 0; h < H_; h++) {
        size_t base = ((size_t)s * H_ + h) * HD_ + 2 * j;
        float q1 = q[base], q2 = q[base + 1];
        q[base]     = q1 * cs - q2 * sn;
        q[base + 1] = q1 * sn + q2 * cs;
        float k1 = k[base], k2 = k[base + 1];
        k[base]     = k1 * cs - k2 * sn;
        k[base + 1] = k1 * sn + k2 * cs;
    }
}

// ---------------- HMMA flash attention ----------------
// BQ=128, BK=64, 8 warps x 16 q-rows, fp16 hi/lo 3-term, fp32 softmax.
#define AQH 0
#define AQL 32768
#define AKH 65536
#define AKL 81920
#define AVH 98304
#define AVL 114688
#define ATTN2_SMEM 131072

__global__ __launch_bounds__(256, 1) void attn2_kernel(
    const float* __restrict__ Q, const float* __restrict__ Kg,
    const float* __restrict__ Vg, __half* __restrict__ Oh, __half* __restrict__ Ol)
{
    extern __shared__ __align__(1024) char sm2[];
    const uint32_t sb = smem_to_u32(sm2);
    const int tid = threadIdx.x, wid = tid >> 5, lane = tid & 31;
    const int h = blockIdx.y;
    const int bq = gridDim.x - 1 - blockIdx.x;   // long CTAs first
    const int q0 = bq * 128;
    const int mat = lane >> 3, rin = lane & 7;
    const float scale = 0.08838834764831845f;

    // load + scale + split Q tile (128 x 128)
    #pragma unroll
    for (int i = 0; i < 8; i++) {
        int idx = tid + i * 256;
        int row = idx >> 4, cc = idx & 15;
        const float* gp = Q + (size_t)(q0 + row) * D_ + h * HD_ + cc * 8;
        float vv[8];
        float4 a = *(const float4*)gp, b = *(const float4*)(gp + 4);
        vv[0] = a.x * scale; vv[1] = a.y * scale; vv[2] = a.z * scale; vv[3] = a.w * scale;
        vv[4] = b.x * scale; vv[5] = b.y * scale; vv[6] = b.z * scale; vv[7] = b.w * scale;
        uint4 hv, lv;
        cvt8(vv, hv, lv);
        uint32_t off = row * 256 + ((cc ^ (row & 7)) << 4);
        *(uint4*)(sm2 + AQH + off) = hv;
        *(uint4*)(sm2 + AQL + off) = lv;
    }

    float m0 = -1e30f, m1 = -1e30f, l0 = 0.f, l1 = 0.f;
    float oacc[16][4] = {};
    const int g0r = q0 + wid * 16 + (lane >> 2);
    const int g1r = g0r + 8;
    const int nk = q0 / 64 + 2;
    __syncthreads();

    for (int kt = 0; kt < nk; kt++) {
        int k0 = kt * 64;
        // load + split K, V tiles (64 x 128 each)
        #pragma unroll
        for (int i = 0; i < 4; i++) {
            int idx = tid + i * 256;
            int row = idx >> 4, cc = idx & 15;
            uint32_t off = row * 256 + ((cc ^ (row & 7)) << 4);
            const float* kp = Kg + (size_t)(k0 + row) * D_ + h * HD_ + cc * 8;
            float vv[8];
            float4 a = *(const float4*)kp, b = *(const float4*)(kp + 4);
            vv[0] = a.x; vv[1] = a.y; vv[2] = a.z; vv[3] = a.w;
            vv[4] = b.x; vv[5] = b.y; vv[6] = b.z; vv[7] = b.w;
            uint4 hv, lv;
            cvt8(vv, hv, lv);
            *(uint4*)(sm2 + AKH + off) = hv;
            *(uint4*)(sm2 + AKL + off) = lv;
            const float* vp = Vg + (size_t)(k0 + row) * D_ + h * HD_ + cc * 8;
            a = *(const float4*)vp; b = *(const float4*)(vp + 4);
            vv[0] = a.x; vv[1] = a.y; vv[2] = a.z; vv[3] = a.w;
            vv[4] = b.x; vv[5] = b.y; vv[6] = b.z; vv[7] = b.w;
            cvt8(vv, hv, lv);
            *(uint4*)(sm2 + AVH + off) = hv;
            *(uint4*)(sm2 + AVL + off) = lv;
        }
        __syncthreads();

        // S = Q K^T (128x64 tile; this warp: 16x64)
        float sacc[8][4] = {};
        #pragma unroll
        for (int kk = 0; kk < 8; kk++) {
            int kk2 = kk << 1;
            int m = wid * 16 + ((mat & 1) << 3) + rin;
            uint32_t ad = sb + AQH + m * 256 + (((kk2 + (mat >> 1)) ^ (m & 7)) << 4);
            uint32_t qa_h[4], qa_l[4];
            LDSM_X4(qa_h[0], qa_h[1], qa_h[2], qa_h[3], ad);
            LDSM_X4(qa_l[0], qa_l[1], qa_l[2], qa_l[3], ad + (AQL - AQH));
            #pragma unroll
            for (int nt = 0; nt < 4; nt++) {
                int n = nt * 16 + ((mat >> 1) << 3) + rin;
                uint32_t bd = sb + AKH + n * 256 + (((kk2 + (mat & 1)) ^ (n & 7)) << 4);
                uint32_t b0, b1, b2, b3, c0, c1, c2, c3;
                LDSM_X4(b0, b1, b2, b3, bd);
                LDSM_X4(c0, c1, c2, c3, bd + (AKL - AKH));
                MMA4(sacc[2 * nt],     qa_h[0], qa_h[1], qa_h[2], qa_h[3], b0, b1);
                MMA4(sacc[2 * nt],     qa_h[0], qa_h[1], qa_h[2], qa_h[3], c0, c1);
                MMA4(sacc[2 * nt],     qa_l[0], qa_l[1], qa_l[2], qa_l[3], b0, b1);
                MMA4(sacc[2 * nt + 1], qa_h[0], qa_h[1], qa_h[2], qa_h[3], b2, b3);
                MMA4(sacc[2 * nt + 1], qa_h[0], qa_h[1], qa_h[2], qa_h[3], c2, c3);
                MMA4(sacc[2 * nt + 1], qa_l[0], qa_l[1], qa_l[2], qa_l[3], b2, b3);
            }
        }

        // causal mask
        if (k0 + 63 > g0r) {
            #pragma unroll
            for (int nt = 0; nt < 8; nt++) {
                int c0 = k0 + nt * 8 + ((lane & 3) << 1);
                if (c0     > g0r) sacc[nt][0] = -1e30f;
                if (c0 + 1 > g0r) sacc[nt][1] = -1e30f;
                if (c0     > g1r) sacc[nt][2] = -1e30f;
                if (c0 + 1 > g1r) sacc[nt][3] = -1e30f;
            }
        }

        // online softmax
        float mx0 = m0, mx1 = m1;
        #pragma unroll
        for (int nt = 0; nt < 8; nt++) {
            mx0 = fmaxf(mx0, fmaxf(sacc[nt][0], sacc[nt][1]));
            mx1 = fmaxf(mx1, fmaxf(sacc[nt][2], sacc[nt][3]));
        }
        mx0 = fmaxf(mx0, __shfl_xor_sync(0xffffffffu, mx0, 1));
        mx0 = fmaxf(mx0, __shfl_xor_sync(0xffffffffu, mx0, 2));
        mx1 = fmaxf(mx1, __shfl_xor_sync(0xffffffffu, mx1, 1));
        mx1 = fmaxf(mx1, __shfl_xor_sync(0xffffffffu, mx1, 2));
        float al0 = __expf(m0 - mx0), al1 = __expf(m1 - mx1);
        m0 = mx0; m1 = mx1;
        float rs0 = 0.f, rs1 = 0.f;
        uint32_t ph0[8], ph1[8], pl0[8], pl1[8];
        #pragma unroll
        for (int nt = 0; nt < 8; nt++) {
            float p0 = __expf(sacc[nt][0] - mx0);
            float p1 = __expf(sacc[nt][1] - mx0);
            float p2 = __expf(sacc[nt][2] - mx1);
            float p3 = __expf(sacc[nt][3] - mx1);
            rs0 += p0 + p1; rs1 += p2 + p3;
            __half h0 = __float2half_rn(p0), h1 = __float2half_rn(p1);
            __half h2 = __float2half_rn(p2), h3 = __float2half_rn(p3);
            ph0[nt] = packh(h0, h1); ph1[nt] = packh(h2, h3);
            pl0[nt] = packh(__float2half_rn(p0 - __half2float(h0)),
                            __float2half_rn(p1 - __half2float(h1)));
            pl1[nt] = packh(__float2half_rn(p2 - __half2float(h2)),
                            __float2half_rn(p3 - __half2float(h3)));
        }
        rs0 += __shfl_xor_sync(0xffffffffu, rs0, 1);
        rs0 += __shfl_xor_sync(0xffffffffu, rs0, 2);
        rs1 += __shfl_xor_sync(0xffffffffu, rs1, 1);
        rs1 += __shfl_xor_sync(0xffffffffu, rs1, 2);
        l0 = l0 * al0 + rs0;
        l1 = l1 * al1 + rs1;
        #pragma unroll
        for (int t = 0; t < 16; t++) {
            oacc[t][0] *= al0; oacc[t][1] *= al0;
            oacc[t][2] *= al1; oacc[t][3] *= al1;
        }

        // O += P @ V
        #pragma unroll
        for (int kk = 0; kk < 4; kk++) {
            uint32_t a0 = ph0[2 * kk], a1 = ph1[2 * kk], a2 = ph0[2 * kk + 1], a3 = ph1[2 * kk + 1];
            uint32_t e0 = pl0[2 * kk], e1 = pl1[2 * kk], e2 = pl0[2 * kk + 1], e3 = pl1[2 * kk + 1];
            #pragma unroll
            for (int ntp = 0; ntp < 8; ntp++) {
                int vrow = kk * 16 + rin + ((mat >> 1) << 3);
                int vch  = 2 * ntp + (mat & 1);
                uint32_t vd = sb + AVH + vrow * 256 + ((vch ^ (vrow & 7)) << 4);
                uint32_t r0, r1, r2, r3, s0, s1, s2, s3;
                LDSM_X4_T(r0, r1, r2, r3, vd);
                LDSM_X4_T(s0, s1, s2, s3, vd + (AVL - AVH));
                MMA4(oacc[2 * ntp],     a0, a1, a2, a3, r0, r2);
                MMA4(oacc[2 * ntp],     a0, a1, a2, a3, s0, s2);
                MMA4(oacc[2 * ntp],     e0, e1, e2, e3, r0, r2);
                MMA4(oacc[2 * ntp + 1], a0, a1, a2, a3, r1, r3);
                MMA4(oacc[2 * ntp + 1], a0, a1, a2, a3, s1, s3);
                MMA4(oacc[2 * ntp + 1], e0, e1, e2, e3, r1, r3);
            }
        }
        __syncthreads();
    }

    // write O (split to h/l fp16)
    float i0 = 1.f / l0, i1 = 1.f / l1;
    #pragma unroll
    for (int t = 0; t < 16; t++) {
        int col = h * HD_ + t * 8 + ((lane & 3) << 1);
        float v0 = oacc[t][0] * i0, v1 = oacc[t][1] * i0;
        float v2 = oacc[t][2] * i1, v3 = oacc[t][3] * i1;
        __half h0 = __float2half_rn(v0), h1 = __float2half_rn(v1);
        __half h2 = __float2half_rn(v2), h3 = __float2half_rn(v3);
        *reinterpret_cast<uint32_t*>(Oh + (size_t)g0r * D_ + col) = packh(h0, h1);
        *reinterpret_cast<uint32_t*>(Oh + (size_t)g1r * D_ + col) = packh(h2, h3);
        *reinterpret_cast<uint32_t*>(Ol + (size_t)g0r * D_ + col) =
            packh(__float2half_rn(v0 - __half2float(h0)), __float2half_rn(v1 - __half2float(h1)));
        *reinterpret_cast<uint32_t*>(Ol + (size_t)g1r * D_ + col) =
            packh(__float2half_rn(v2 - __half2float(h2)), __float2half_rn(v3 - __half2float(h3)));
    }
}

// ---------------- SiLU(gate) * up with fused split output ----------------
__global__ void silu_split_kernel(const float* __restrict__ g, const float* __restrict__ u,
                                  __half* __restrict__ oh, __half* __restrict__ ol, int n8)
{
    int i = blockIdx.x * blockDim.x + threadIdx.x;
    if (i < n8) {
        float4 g0 = ((const float4*)g)[2 * i], g1 = ((const float4*)g)[2 * i + 1];
        float4 u0 = ((const float4*)u)[2 * i], u1 = ((const float4*)u)[2 * i + 1];
        float vv[8];
        vv[0] = g0.x / (1.f + __expf(-g0.x)) * u0.x;
        vv[1] = g0.y / (1.f + __expf(-g0.y)) * u0.y;
        vv[2] = g0.z / (1.f + __expf(-g0.z)) * u0.z;
        vv[3] = g0.w / (1.f + __expf(-g0.w)) * u0.w;
        vv[4] = g1.x / (1.f + __expf(-g1.x)) * u1.x;
        vv[5] = g1.y / (1.f + __expf(-g1.y)) * u1.y;
        vv[6] = g1.z / (1.f + __expf(-g1.z)) * u1.z;
        vv[7] = g1.w / (1.f + __expf(-g1.w)) * u1.w;
        uint4 hv, lv;
        cvt8(vv, hv, lv);
        ((uint4*)oh)[i] = hv;
        ((uint4*)ol)[i] = lv;
    }
}

// ---------------- launch ----------------
extern "C" void kernel_launch(void* const* d_in, const int* in_sizes, int n_in,
                              void* d_out, int out_size)
{
    const float* x      = (const float*)d_in[0];
    const float* ln_w   = (const float*)d_in[1];
    const float* ffln_w = (const float*)d_in[2];
    const float* wq     = (const float*)d_in[3];
    const float* wk     = (const float*)d_in[4];
    const float* wv     = (const float*)d_in[5];
    const float* wo     = (const float*)d_in[6];
    const float* wg     = (const float*)d_in[7];
    const float* w1     = (const float*)d_in[8];
    const float* w2     = (const float*)d_in[9];
    float* out = (float*)d_out;

    float *q, *k, *v, *x2, *gate, *up;
    cudaGetSymbolAddress((void**)&q,    g_q);
    cudaGetSymbolAddress((void**)&k,    g_k);
    cudaGetSymbolAddress((void**)&v,    g_v);
    cudaGetSymbolAddress((void**)&x2,   g_x2);
    cudaGetSymbolAddress((void**)&gate, g_gate);
    cudaGetSymbolAddress((void**)&up,   g_up);

    __half *wqt_h, *wqt_l, *wkt_h, *wkt_l, *wvt_h, *wvt_l, *wot_h, *wot_l;
    __half *wgt_h, *wgt_l, *w1t_h, *w1t_l, *w2t_h, *w2t_l, *a_h, *a_l;
    cudaGetSymbolAddress((void**)&wqt_h, g_wqt_h); cudaGetSymbolAddress((void**)&wqt_l, g_wqt_l);
    cudaGetSymbolAddress((void**)&wkt_h, g_wkt_h); cudaGetSymbolAddress((void**)&wkt_l, g_wkt_l);
    cudaGetSymbolAddress((void**)&wvt_h, g_wvt_h); cudaGetSymbolAddress((void**)&wvt_l, g_wvt_l);
    cudaGetSymbolAddress((void**)&wot_h, g_wot_h); cudaGetSymbolAddress((void**)&wot_l, g_wot_l);
    cudaGetSymbolAddress((void**)&wgt_h, g_wgt_h); cudaGetSymbolAddress((void**)&wgt_l, g_wgt_l);
    cudaGetSymbolAddress((void**)&w1t_h, g_w1t_h); cudaGetSymbolAddress((void**)&w1t_l, g_w1t_l);
    cudaGetSymbolAddress((void**)&w2t_h, g_w2t_h); cudaGetSymbolAddress((void**)&w2t_l, g_w2t_l);
    cudaGetSymbolAddress((void**)&a_h, g_a_h);     cudaGetSymbolAddress((void**)&a_l, g_a_l);

    cudaFuncSetAttribute(attn2_kernel, cudaFuncAttributeMaxDynamicSharedMemorySize, ATTN2_SMEM);
    cudaFuncSetAttribute(hgemm<false>, cudaFuncAttributeMaxDynamicSharedMemorySize, HGEMM_SMEM);
    cudaFuncSetAttribute(hgemm<true>,  cudaFuncAttributeMaxDynamicSharedMemorySize, HGEMM_SMEM);

    // weight prep: transpose + hi/lo split (fp16)
    dim3 wt(32, 8);
    wsplit_kernel<<<dim3(D_ / 32, D_ / 32), wt>>>(wq, wqt_h, wqt_l, D_, D_);
    wsplit_kernel<<<dim3(D_ / 32, D_ / 32), wt>>>(wk, wkt_h, wkt_l, D_, D_);
    wsplit_kernel<<<dim3(D_ / 32, D_ / 32), wt>>>(wv, wvt_h, wvt_l, D_, D_);
    wsplit_kernel<<<dim3(D_ / 32, D_ / 32), wt>>>(wo, wot_h, wot_l, D_, D_);
    wsplit_kernel<<<dim3(FF_ / 32, D_ / 32), wt>>>(wg, wgt_h, wgt_l, D_, FF_);
    wsplit_kernel<<<dim3(FF_ / 32, D_ / 32), wt>>>(w1, w1t_h, w1t_l, D_, FF_);
    wsplit_kernel<<<dim3(D_ / 32, FF_ / 32), wt>>>(w2, w2t_h, w2t_l, FF_, D_);

    // xn = rmsnorm(x) -> a_h/a_l
    rmsnorm_split_kernel<<<S_, 256>>>(x, ln_w, a_h, a_l);

    // q,k,v projections
    dim3 gdd(S_ / 128, D_ / 256);
    hgemm<false><<<gdd, 256, HGEMM_SMEM>>>(S_, D_, D_, a_h, a_l, wqt_h, wqt_l, nullptr, q);
    hgemm<false><<<gdd, 256, HGEMM_SMEM>>>(S_, D_, D_, a_h, a_l, wkt_h, wkt_l, nullptr, k);
    hgemm<false><<<gdd, 256, HGEMM_SMEM>>>(S_, D_, D_, a_h, a_l, wvt_h, wvt_l, nullptr, v);

    // rope + attention (attention writes split fp16 O into a_h/a_l)
    rope_kernel<<<S_, 64>>>(q, k);
    attn2_kernel<<<dim3(S_ / 128, H_), 256, ATTN2_SMEM>>>(q, k, v, a_h, a_l);

    // x2 = attn @ wo + x
    hgemm<true><<<gdd, 256, HGEMM_SMEM>>>(S_, D_, D_, a_h, a_l, wot_h, wot_l, x, x2);

    // xn2 = rmsnorm(x2) -> a_h/a_l
    rmsnorm_split_kernel<<<S_, 256>>>(x2, ffln_w, a_h, a_l);

    // gate/up projections
    dim3 gdf(S_ / 128, FF_ / 256);
    hgemm<false><<<gdf, 256, HGEMM_SMEM>>>(S_, FF_, D_, a_h, a_l, wgt_h, wgt_l, nullptr, gate);
    hgemm<false><<<gdf, 256, HGEMM_SMEM>>>(S_, FF_, D_, a_h, a_l, w1t_h, w1t_l, nullptr, up);

    // h = silu(gate) * up -> a_h/a_l
    int n8 = (S_ * FF_) / 8;
    silu_split_kernel<<<(n8 + 255) / 256, 256>>>(gate, up, a_h, a_l, n8);

    // out = h @ w2 + x2
    hgemm<true><<<dim3(S_ / 128, D_ / 256), 256, HGEMM_SMEM>>>(S_, D_, FF_, a_h, a_l, w2t_h, w2t_l, x2, out);
}

// round 5
// speedup vs baseline: 1.4545x; 1.4545x over previous
#include <cuda_runtime.h>
#include <cuda_fp16.h>
#include <cstdint>
#include <math.h>

#define S_  2048
#define D_  4096
#define H_  32
#define HD_ 128
#define FF_ 11008

// ---------------- scratch (no allocations allowed) ----------------
__device__ float g_q   [(size_t)S_ * D_];
__device__ float g_k   [(size_t)S_ * D_];
__device__ float g_v   [(size_t)S_ * D_];
__device__ float g_x2  [(size_t)S_ * D_];
__device__ float g_gate[(size_t)S_ * FF_];
__device__ float g_up  [(size_t)S_ * FF_];

// transposed + hi/lo split weights (fp16), layout [N, K] row-major
__device__ __half g_wqt_h[(size_t)D_ * D_];
__device__ __half g_wqt_l[(size_t)D_ * D_];
__device__ __half g_wkt_h[(size_t)D_ * D_];
__device__ __half g_wkt_l[(size_t)D_ * D_];
__device__ __half g_wvt_h[(size_t)D_ * D_];
__device__ __half g_wvt_l[(size_t)D_ * D_];
__device__ __half g_wot_h[(size_t)D_ * D_];
__device__ __half g_wot_l[(size_t)D_ * D_];
__device__ __half g_wgt_h[(size_t)FF_ * D_];
__device__ __half g_wgt_l[(size_t)FF_ * D_];
__device__ __half g_w1t_h[(size_t)FF_ * D_];
__device__ __half g_w1t_l[(size_t)FF_ * D_];
__device__ __half g_w2t_h[(size_t)D_ * FF_];
__device__ __half g_w2t_l[(size_t)D_ * FF_];

// activation hi/lo split scratch (reused sequentially)
__device__ __half g_a_h[(size_t)S_ * FF_];
__device__ __half g_a_l[(size_t)S_ * FF_];

// ---------------- asm helpers ----------------
__device__ __forceinline__ uint32_t smem_to_u32(const void* p) {
    uint32_t a;
    asm("{ .reg .u64 t; cvta.to.shared.u64 t, %1; cvt.u32.u64 %0, t; }" : "=r"(a) : "l"(p));
    return a;
}
__device__ __forceinline__ void cp16(uint32_t saddr, const void* gaddr) {
    asm volatile("cp.async.cg.shared.global [%0], [%1], 16;" :: "r"(saddr), "l"(gaddr));
}
#define CP_COMMIT() asm volatile("cp.async.commit_group;" ::: "memory")
#define CP_WAIT(n)  asm volatile("cp.async.wait_group %0;" :: "n"(n) : "memory")

#define LDSM_X4(r0, r1, r2, r3, addr) \
    asm volatile("ldmatrix.sync.aligned.m8n8.x4.shared.b16 {%0,%1,%2,%3}, [%4];" \
        : "=r"(r0), "=r"(r1), "=r"(r2), "=r"(r3) : "r"(addr))
#define LDSM_X4_T(r0, r1, r2, r3, addr) \
    asm volatile("ldmatrix.sync.aligned.m8n8.x4.trans.shared.b16 {%0,%1,%2,%3}, [%4];" \
        : "=r"(r0), "=r"(r1), "=r"(r2), "=r"(r3) : "r"(addr))

#define MMA16816(d, a, b) \
    asm volatile("mma.sync.aligned.m16n8k16.row.col.f32.f16.f16.f32 " \
        "{%0,%1,%2,%3}, {%4,%5,%6,%7}, {%8,%9}, {%0,%1,%2,%3};" \
        : "+f"((d)[0]), "+f"((d)[1]), "+f"((d)[2]), "+f"((d)[3]) \
        : "r"((a)[0]), "r"((a)[1]), "r"((a)[2]), "r"((a)[3]), "r"((b)[0]), "r"((b)[1]))
#define MMA4(d, a0, a1, a2, a3, b0, b1) \
    asm volatile("mma.sync.aligned.m16n8k16.row.col.f32.f16.f16.f32 " \
        "{%0,%1,%2,%3}, {%4,%5,%6,%7}, {%8,%9}, {%0,%1,%2,%3};" \
        : "+f"((d)[0]), "+f"((d)[1]), "+f"((d)[2]), "+f"((d)[3]) \
        : "r"(a0), "r"(a1), "r"(a2), "r"(a3), "r"(b0), "r"(b1))

__device__ __forceinline__ uint32_t packh(__half a, __half b) {
    return ((uint32_t)__half_as_ushort(b) << 16) | __half_as_ushort(a);
}
// 8 floats -> 16B hi chunk + 16B lo chunk
__device__ __forceinline__ void cvt8(const float* v, uint4& hv, uint4& lv) {
    uint32_t hh[4], ll[4];
    #pragma unroll
    for (int j = 0; j < 4; j++) {
        float a = v[2 * j], b = v[2 * j + 1];
        __half ha = __float2half_rn(a), hb = __float2half_rn(b);
        __half la = __float2half_rn(a - __half2float(ha));
        __half lb = __float2half_rn(b - __half2float(hb));
        hh[j] = packh(ha, hb); ll[j] = packh(la, lb);
    }
    hv = make_uint4(hh[0], hh[1], hh[2], hh[3]);
    lv = make_uint4(ll[0], ll[1], ll[2], ll[3]);
}

// ---------------- weight transpose + hi/lo split ----------------
__global__ __launch_bounds__(256) void wsplit_kernel(
    const float* __restrict__ W, __half* __restrict__ Wh,
    __half* __restrict__ Wl, int K, int N)
{
    __shared__ float t[32][33];
    int n0 = blockIdx.x * 32, k0 = blockIdx.y * 32;
    int tx = threadIdx.x, ty = threadIdx.y; // (32, 8)
    #pragma unroll
    for (int i = 0; i < 4; i++)
        t[ty + 8 * i][tx] = W[(size_t)(k0 + ty + 8 * i) * N + n0 + tx];
    __syncthreads();
    #pragma unroll
    for (int i = 0; i < 4; i++) {
        float v = t[tx][ty + 8 * i];
        __half hi = __float2half_rn(v);
        __half lo = __float2half_rn(v - __half2float(hi));
        size_t o = (size_t)(n0 + ty + 8 * i) * K + k0 + tx;
        Wh[o] = hi; Wl[o] = lo;
    }
}

// ---------------- HMMA GEMM (R3 proven config): CTA 128x128, BK=64, 3-stage ----------------
#define STAGES 3
#define OPBYTES 16384                 // 128 rows x 64 f16 = 16KB
#define STAGE_BYTES (4 * OPBYTES)     // Ah | Al | Bh | Bl
#define HGEMM_SMEM (STAGES * STAGE_BYTES)

template <bool RESID>
__global__ __launch_bounds__(256) void hgemm(
    int M, int N, int K,
    const __half* __restrict__ Ah, const __half* __restrict__ Al,
    const __half* __restrict__ Bh, const __half* __restrict__ Bl,
    const float* __restrict__ Rsd, float* __restrict__ C)
{
    extern __shared__ __align__(1024) char smem[];
    const int tid  = threadIdx.x;
    const int wid  = tid >> 5;
    const int lane = tid & 31;
    const int m0 = blockIdx.x * 128;
    const int n0 = blockIdx.y * 128;
    const int nk = K >> 6;
    const uint32_t sbase = smem_to_u32(smem);

    const int wm = (wid & 3) * 32;   // warp M offset
    const int wn = (wid >> 2) * 64;  // warp N offset

    const __half* Abase_h = Ah + (size_t)m0 * K;
    const __half* Abase_l = Al + (size_t)m0 * K;
    const __half* Bbase_h = Bh + (size_t)n0 * K;
    const __half* Bbase_l = Bl + (size_t)n0 * K;

    // per-thread load coords (4 chunks of 16B per operand)
    int lrow[4], lcc[4];
    uint32_t lsoff[4];
    #pragma unroll
    for (int t = 0; t < 4; t++) {
        int c = tid + t * 256;
        lrow[t] = c >> 3;
        lcc[t]  = c & 7;
        lsoff[t] = lrow[t] * 128 + (((lcc[t] ^ (lrow[t] & 7))) << 4);
    }

    #define ISSUE(s, kt) do { \
        uint32_t sb_ = sbase + (s) * STAGE_BYTES; \
        size_t kofs_ = (size_t)(kt) << 6; \
        _Pragma("unroll") \
        for (int t = 0; t < 4; t++) { \
            size_t go_ = (size_t)lrow[t] * K + kofs_ + lcc[t] * 8; \
            uint32_t so_ = sb_ + lsoff[t]; \
            cp16(so_,               Abase_h + go_); \
            cp16(so_ + OPBYTES,     Abase_l + go_); \
            cp16(so_ + 2 * OPBYTES, Bbase_h + go_); \
            cp16(so_ + 3 * OPBYTES, Bbase_l + go_); \
        } \
    } while (0)

    float acc[2][8][4] = {};

    #pragma unroll
    for (int s = 0; s < STAGES - 1; s++) { ISSUE(s, s); CP_COMMIT(); }

    const int mat = lane >> 3, rin = lane & 7;

    for (int i = 0; i < nk; i++) {
        CP_WAIT(STAGES - 2);
        __syncthreads();
        if (i + STAGES - 1 < nk) { ISSUE((i + STAGES - 1) % STAGES, i + STAGES - 1); }
        CP_COMMIT();

        uint32_t stg = sbase + (i % STAGES) * STAGE_BYTES;
        #pragma unroll
        for (int ks = 0; ks < 4; ks++) {
            int ks2 = ks << 1;
            uint32_t fa_h[2][4], fa_l[2][4], fb_h[8][2], fb_l[8][2];
            #pragma unroll
            for (int mt = 0; mt < 2; mt++) {
                int m = wm + mt * 16 + ((mat & 1) << 3) + rin;
                uint32_t ad = stg + m * 128 + (((ks2 + (mat >> 1)) ^ (m & 7)) << 4);
                LDSM_X4(fa_h[mt][0], fa_h[mt][1], fa_h[mt][2], fa_h[mt][3], ad);
                LDSM_X4(fa_l[mt][0], fa_l[mt][1], fa_l[mt][2], fa_l[mt][3], ad + OPBYTES);
            }
            #pragma unroll
            for (int p = 0; p < 4; p++) {
                int n = wn + p * 16 + ((mat >> 1) << 3) + rin;
                uint32_t bd = stg + 2 * OPBYTES + n * 128 + (((ks2 + (mat & 1)) ^ (n & 7)) << 4);
                uint32_t r0, r1, r2, r3;
                LDSM_X4(r0, r1, r2, r3, bd);
                fb_h[p * 2][0] = r0; fb_h[p * 2][1] = r1;
                fb_h[p * 2 + 1][0] = r2; fb_h[p * 2 + 1][1] = r3;
                LDSM_X4(r0, r1, r2, r3, bd + OPBYTES);
                fb_l[p * 2][0] = r0; fb_l[p * 2][1] = r1;
                fb_l[p * 2 + 1][0] = r2; fb_l[p * 2 + 1][1] = r3;
            }
            #pragma unroll
            for (int mt = 0; mt < 2; mt++)
                #pragma unroll
                for (int nt = 0; nt < 8; nt++) {
                    MMA16816(acc[mt][nt], fa_h[mt], fb_h[nt]);
                    MMA16816(acc[mt][nt], fa_h[mt], fb_l[nt]);
                    MMA16816(acc[mt][nt], fa_l[mt], fb_h[nt]);
                }
        }
        __syncthreads();
    }
    #undef ISSUE

    int qr = lane >> 2, qc = (lane & 3) << 1;
    #pragma unroll
    for (int mt = 0; mt < 2; mt++) {
        #pragma unroll
        for (int nt = 0; nt < 8; nt++) {
            int r0 = m0 + wm + mt * 16 + qr;
            int cc = n0 + wn + nt * 8 + qc;
            float2 v0 = make_float2(acc[mt][nt][0], acc[mt][nt][1]);
            float2 v1 = make_float2(acc[mt][nt][2], acc[mt][nt][3]);
            if (RESID) {
                float2 a = *(const float2*)(Rsd + (size_t)r0 * N + cc);
                float2 b = *(const float2*)(Rsd + (size_t)(r0 + 8) * N + cc);
                v0.x += a.x; v0.y += a.y; v1.x += b.x; v1.y += b.y;
            }
            *(float2*)(C + (size_t)r0 * N + cc)       = v0;
            *(float2*)(C + (size_t)(r0 + 8) * N + cc) = v1;
        }
    }
}

// ---------------- RMSNorm with fused fp16 hi/lo split output ----------------
__global__ __launch_bounds__(256) void rmsnorm_split_kernel(
    const float* __restrict__ x, const float* __restrict__ w,
    __half* __restrict__ oh, __half* __restrict__ ol)
{
    int row = blockIdx.x;
    const float4* xr = (const float4*)(x + (size_t)row * D_);
    float ss = 0.f;
    #pragma unroll 4
    for (int i = threadIdx.x; i < D_ / 4; i += 256) {
        float4 v = xr[i];
        ss += v.x * v.x + v.y * v.y + v.z * v.z + v.w * v.w;
    }
    __shared__ float red[8];
    #pragma unroll
    for (int o = 16; o; o >>= 1) ss += __shfl_xor_sync(0xffffffffu, ss, o);
    if ((threadIdx.x & 31) == 0) red[threadIdx.x >> 5] = ss;
    __syncthreads();
    if (threadIdx.x == 0) {
        float t = 0.f;
        #pragma unroll
        for (int i = 0; i < 8; i++) t += red[i];
        red[0] = rsqrtf(t / (float)D_ + 1e-5f);
    }
    __syncthreads();
    float inv = red[0];
    const float4* wr = (const float4*)w;
    for (int i = threadIdx.x; i < D_ / 8; i += 256) {
        float vv[8];
        float4 a = xr[2 * i], b = xr[2 * i + 1];
        float4 wa = wr[2 * i], wb = wr[2 * i + 1];
        vv[0] = a.x * inv * wa.x; vv[1] = a.y * inv * wa.y;
        vv[2] = a.z * inv * wa.z; vv[3] = a.w * inv * wa.w;
        vv[4] = b.x * inv * wb.x; vv[5] = b.y * inv * wb.y;
        vv[6] = b.z * inv * wb.z; vv[7] = b.w * inv * wb.w;
        uint4 hv, lv;
        cvt8(vv, hv, lv);
        ((uint4*)(oh + (size_t)row * D_))[i] = hv;
        ((uint4*)(ol + (size_t)row * D_))[i] = lv;
    }
}

// ---------------- RoPE (q and k in place, fp32) ----------------
__global__ void rope_kernel(float* __restrict__ q, float* __restrict__ k)
{
    int s = blockIdx.x;
    int j = threadIdx.x;   // 0..63 pair index
    float inv = (float)exp((double)j * -0.14391156831212787);
    float ang = (float)s * inv;
    float sn, cs;
    sincosf(ang, &sn, &cs);
    #pragma unroll 4
    for (int h = 0; h < H_; h++) {
        size_t base = ((size_t)s * H_ + h) * HD_ + 2 * j;
        float q1 = q[base], q2 = q[base + 1];
        q[base]     = q1 * cs - q2 * sn;
        q[base + 1] = q1 * sn + q2 * cs;
        float k1 = k[base], k2 = k[base + 1];
        k[base]     = k1 * cs - k2 * sn;
        k[base + 1] = k1 * sn + k2 * cs;
    }
}

// ---------------- HMMA flash attention ----------------
// BQ=128, BK=64, 8 warps x 16 q-rows, fp16 hi/lo 3-term, fp32 softmax.
#define AQH 0
#define AQL 32768
#define AKH 65536
#define AKL 81920
#define AVH 98304
#define AVL 114688
#define ATTN2_SMEM 131072

__global__ __launch_bounds__(256, 1) void attn2_kernel(
    const float* __restrict__ Q, const float* __restrict__ Kg,
    const float* __restrict__ Vg, __half* __restrict__ Oh, __half* __restrict__ Ol)
{
    extern __shared__ __align__(1024) char sm2[];
    const uint32_t sb = smem_to_u32(sm2);
    const int tid = threadIdx.x, wid = tid >> 5, lane = tid & 31;
    const int h = blockIdx.y;
    const int bq = gridDim.x - 1 - blockIdx.x;   // long CTAs first
    const int q0 = bq * 128;
    const int mat = lane >> 3, rin = lane & 7;
    const float scale = 0.08838834764831845f;

    // load + scale + split Q tile (128 x 128)
    #pragma unroll
    for (int i = 0; i < 8; i++) {
        int idx = tid + i * 256;
        int row = idx >> 4, cc = idx & 15;
        const float* gp = Q + (size_t)(q0 + row) * D_ + h * HD_ + cc * 8;
        float vv[8];
        float4 a = *(const float4*)gp, b = *(const float4*)(gp + 4);
        vv[0] = a.x * scale; vv[1] = a.y * scale; vv[2] = a.z * scale; vv[3] = a.w * scale;
        vv[4] = b.x * scale; vv[5] = b.y * scale; vv[6] = b.z * scale; vv[7] = b.w * scale;
        uint4 hv, lv;
        cvt8(vv, hv, lv);
        uint32_t off = row * 256 + ((cc ^ (row & 7)) << 4);
        *(uint4*)(sm2 + AQH + off) = hv;
        *(uint4*)(sm2 + AQL + off) = lv;
    }

    float m0 = -1e30f, m1 = -1e30f, l0 = 0.f, l1 = 0.f;
    float oacc[16][4] = {};
    const int g0r = q0 + wid * 16 + (lane >> 2);
    const int g1r = g0r + 8;
    const int nk = q0 / 64 + 2;
    __syncthreads();

    for (int kt = 0; kt < nk; kt++) {
        int k0 = kt * 64;
        // load + split K, V tiles (64 x 128 each)
        #pragma unroll
        for (int i = 0; i < 4; i++) {
            int idx = tid + i * 256;
            int row = idx >> 4, cc = idx & 15;
            uint32_t off = row * 256 + ((cc ^ (row & 7)) << 4);
            const float* kp = Kg + (size_t)(k0 + row) * D_ + h * HD_ + cc * 8;
            float vv[8];
            float4 a = *(const float4*)kp, b = *(const float4*)(kp + 4);
            vv[0] = a.x; vv[1] = a.y; vv[2] = a.z; vv[3] = a.w;
            vv[4] = b.x; vv[5] = b.y; vv[6] = b.z; vv[7] = b.w;
            uint4 hv, lv;
            cvt8(vv, hv, lv);
            *(uint4*)(sm2 + AKH + off) = hv;
            *(uint4*)(sm2 + AKL + off) = lv;
            const float* vp = Vg + (size_t)(k0 + row) * D_ + h * HD_ + cc * 8;
            a = *(const float4*)vp; b = *(const float4*)(vp + 4);
            vv[0] = a.x; vv[1] = a.y; vv[2] = a.z; vv[3] = a.w;
            vv[4] = b.x; vv[5] = b.y; vv[6] = b.z; vv[7] = b.w;
            cvt8(vv, hv, lv);
            *(uint4*)(sm2 + AVH + off) = hv;
            *(uint4*)(sm2 + AVL + off) = lv;
        }
        __syncthreads();

        // S = Q K^T (this warp: 16x64)
        float sacc[8][4] = {};
        #pragma unroll
        for (int kk = 0; kk < 8; kk++) {
            int kk2 = kk << 1;
            int m = wid * 16 + ((mat & 1) << 3) + rin;
            uint32_t ad = sb + AQH + m * 256 + (((kk2 + (mat >> 1)) ^ (m & 7)) << 4);
            uint32_t qa_h[4], qa_l[4];
            LDSM_X4(qa_h[0], qa_h[1], qa_h[2], qa_h[3], ad);
            LDSM_X4(qa_l[0], qa_l[1], qa_l[2], qa_l[3], ad + (AQL - AQH));
            #pragma unroll
            for (int nt = 0; nt < 4; nt++) {
                int n = nt * 16 + ((mat >> 1) << 3) + rin;
                uint32_t bd = sb + AKH + n * 256 + (((kk2 + (mat & 1)) ^ (n & 7)) << 4);
                uint32_t b0, b1, b2, b3, c0, c1, c2, c3;
                LDSM_X4(b0, b1, b2, b3, bd);
                LDSM_X4(c0, c1, c2, c3, bd + (AKL - AKH));
                MMA4(sacc[2 * nt],     qa_h[0], qa_h[1], qa_h[2], qa_h[3], b0, b1);
                MMA4(sacc[2 * nt],     qa_h[0], qa_h[1], qa_h[2], qa_h[3], c0, c1);
                MMA4(sacc[2 * nt],     qa_l[0], qa_l[1], qa_l[2], qa_l[3], b0, b1);
                MMA4(sacc[2 * nt + 1], qa_h[0], qa_h[1], qa_h[2], qa_h[3], b2, b3);
                MMA4(sacc[2 * nt + 1], qa_h[0], qa_h[1], qa_h[2], qa_h[3], c2, c3);
                MMA4(sacc[2 * nt + 1], qa_l[0], qa_l[1], qa_l[2], qa_l[3], b2, b3);
            }
        }

        // causal mask
        if (k0 + 63 > g0r) {
            #pragma unroll
            for (int nt = 0; nt < 8; nt++) {
                int c0 = k0 + nt * 8 + ((lane & 3) << 1);
                if (c0     > g0r) sacc[nt][0] = -1e30f;
                if (c0 + 1 > g0r) sacc[nt][1] = -1e30f;
                if (c0     > g1r) sacc[nt][2] = -1e30f;
                if (c0 + 1 > g1r) sacc[nt][3] = -1e30f;
            }
        }

        // online softmax
        float mx0 = m0, mx1 = m1;
        #pragma unroll
        for (int nt = 0; nt < 8; nt++) {
            mx0 = fmaxf(mx0, fmaxf(sacc[nt][0], sacc[nt][1]));
            mx1 = fmaxf(mx1, fmaxf(sacc[nt][2], sacc[nt][3]));
        }
        mx0 = fmaxf(mx0, __shfl_xor_sync(0xffffffffu, mx0, 1));
        mx0 = fmaxf(mx0, __shfl_xor_sync(0xffffffffu, mx0, 2));
        mx1 = fmaxf(mx1, __shfl_xor_sync(0xffffffffu, mx1, 1));
        mx1 = fmaxf(mx1, __shfl_xor_sync(0xffffffffu, mx1, 2));
        float al0 = __expf(m0 - mx0), al1 = __expf(m1 - mx1);
        m0 = mx0; m1 = mx1;
        float rs0 = 0.f, rs1 = 0.f;
        uint32_t ph0[8], ph1[8], pl0[8], pl1[8];
        #pragma unroll
        for (int nt = 0; nt < 8; nt++) {
            float p0 = __expf(sacc[nt][0] - mx0);
            float p1 = __expf(sacc[nt][1] - mx0);
            float p2 = __expf(sacc[nt][2] - mx1);
            float p3 = __expf(sacc[nt][3] - mx1);
            rs0 += p0 + p1; rs1 += p2 + p3;
            __half h0 = __float2half_rn(p0), h1 = __float2half_rn(p1);
            __half h2 = __float2half_rn(p2), h3 = __float2half_rn(p3);
            ph0[nt] = packh(h0, h1); ph1[nt] = packh(h2, h3);
            pl0[nt] = packh(__float2half_rn(p0 - __half2float(h0)),
                            __float2half_rn(p1 - __half2float(h1)));
            pl1[nt] = packh(__float2half_rn(p2 - __half2float(h2)),
                            __float2half_rn(p3 - __half2float(h3)));
        }
        rs0 += __shfl_xor_sync(0xffffffffu, rs0, 1);
        rs0 += __shfl_xor_sync(0xffffffffu, rs0, 2);
        rs1 += __shfl_xor_sync(0xffffffffu, rs1, 1);
        rs1 += __shfl_xor_sync(0xffffffffu, rs1, 2);
        l0 = l0 * al0 + rs0;
        l1 = l1 * al1 + rs1;
        #pragma unroll
        for (int t = 0; t < 16; t++) {
            oacc[t][0] *= al0; oacc[t][1] *= al0;
            oacc[t][2] *= al1; oacc[t][3] *= al1;
        }

        // O += P @ V
        #pragma unroll
        for (int kk = 0; kk < 4; kk++) {
            uint32_t a0 = ph0[2 * kk], a1 = ph1[2 * kk], a2 = ph0[2 * kk + 1], a3 = ph1[2 * kk + 1];
            uint32_t e0 = pl0[2 * kk], e1 = pl1[2 * kk], e2 = pl0[2 * kk + 1], e3 = pl1[2 * kk + 1];
            #pragma unroll
            for (int ntp = 0; ntp < 8; ntp++) {
                int vrow = kk * 16 + rin + ((mat >> 1) << 3);
                int vch  = 2 * ntp + (mat & 1);
                uint32_t vd = sb + AVH + vrow * 256 + ((vch ^ (vrow & 7)) << 4);
                uint32_t r0, r1, r2, r3, s0, s1, s2, s3;
                LDSM_X4_T(r0, r1, r2, r3, vd);
                LDSM_X4_T(s0, s1, s2, s3, vd + (AVL - AVH));
                MMA4(oacc[2 * ntp],     a0, a1, a2, a3, r0, r2);
                MMA4(oacc[2 * ntp],     a0, a1, a2, a3, s0, s2);
                MMA4(oacc[2 * ntp],     e0, e1, e2, e3, r0, r2);
                MMA4(oacc[2 * ntp + 1], a0, a1, a2, a3, r1, r3);
                MMA4(oacc[2 * ntp + 1], a0, a1, a2, a3, s1, s3);
                MMA4(oacc[2 * ntp + 1], e0, e1, e2, e3, r1, r3);
            }
        }
        __syncthreads();
    }

    // write O (split to h/l fp16)
    float i0 = 1.f / l0, i1 = 1.f / l1;
    #pragma unroll
    for (int t = 0; t < 16; t++) {
        int col = h * HD_ + t * 8 + ((lane & 3) << 1);
        float v0 = oacc[t][0] * i0, v1 = oacc[t][1] * i0;
        float v2 = oacc[t][2] * i1, v3 = oacc[t][3] * i1;
        __half h0 = __float2half_rn(v0), h1 = __float2half_rn(v1);
        __half h2 = __float2half_rn(v2), h3 = __float2half_rn(v3);
        *reinterpret_cast<uint32_t*>(Oh + (size_t)g0r * D_ + col) = packh(h0, h1);
        *reinterpret_cast<uint32_t*>(Oh + (size_t)g1r * D_ + col) = packh(h2, h3);
        *reinterpret_cast<uint32_t*>(Ol + (size_t)g0r * D_ + col) =
            packh(__float2half_rn(v0 - __half2float(h0)), __float2half_rn(v1 - __half2float(h1)));
        *reinterpret_cast<uint32_t*>(Ol + (size_t)g1r * D_ + col) =
            packh(__float2half_rn(v2 - __half2float(h2)), __float2half_rn(v3 - __half2float(h3)));
    }
}

// ---------------- SiLU(gate) * up with fused split output ----------------
__global__ void silu_split_kernel(const float* __restrict__ g, const float* __restrict__ u,
                                  __half* __restrict__ oh, __half* __restrict__ ol, int n8)
{
    int i = blockIdx.x * blockDim.x + threadIdx.x;
    if (i < n8) {
        float4 g0 = ((const float4*)g)[2 * i], g1 = ((const float4*)g)[2 * i + 1];
        float4 u0 = ((const float4*)u)[2 * i], u1 = ((const float4*)u)[2 * i + 1];
        float vv[8];
        vv[0] = g0.x / (1.f + __expf(-g0.x)) * u0.x;
        vv[1] = g0.y / (1.f + __expf(-g0.y)) * u0.y;
        vv[2] = g0.z / (1.f + __expf(-g0.z)) * u0.z;
        vv[3] = g0.w / (1.f + __expf(-g0.w)) * u0.w;
        vv[4] = g1.x / (1.f + __expf(-g1.x)) * u1.x;
        vv[5] = g1.y / (1.f + __expf(-g1.y)) * u1.y;
        vv[6] = g1.z / (1.f + __expf(-g1.z)) * u1.z;
        vv[7] = g1.w / (1.f + __expf(-g1.w)) * u1.w;
        uint4 hv, lv;
        cvt8(vv, hv, lv);
        ((uint4*)oh)[i] = hv;
        ((uint4*)ol)[i] = lv;
    }
}

// ---------------- launch ----------------
extern "C" void kernel_launch(void* const* d_in, const int* in_sizes, int n_in,
                              void* d_out, int out_size)
{
    const float* x      = (const float*)d_in[0];
    const float* ln_w   = (const float*)d_in[1];
    const float* ffln_w = (const float*)d_in[2];
    const float* wq     = (const float*)d_in[3];
    const float* wk     = (const float*)d_in[4];
    const float* wv     = (const float*)d_in[5];
    const float* wo     = (const float*)d_in[6];
    const float* wg     = (const float*)d_in[7];
    const float* w1     = (const float*)d_in[8];
    const float* w2     = (const float*)d_in[9];
    float* out = (float*)d_out;

    float *q, *k, *v, *x2, *gate, *up;
    cudaGetSymbolAddress((void**)&q,    g_q);
    cudaGetSymbolAddress((void**)&k,    g_k);
    cudaGetSymbolAddress((void**)&v,    g_v);
    cudaGetSymbolAddress((void**)&x2,   g_x2);
    cudaGetSymbolAddress((void**)&gate, g_gate);
    cudaGetSymbolAddress((void**)&up,   g_up);

    __half *wqt_h, *wqt_l, *wkt_h, *wkt_l, *wvt_h, *wvt_l, *wot_h, *wot_l;
    __half *wgt_h, *wgt_l, *w1t_h, *w1t_l, *w2t_h, *w2t_l, *a_h, *a_l;
    cudaGetSymbolAddress((void**)&wqt_h, g_wqt_h); cudaGetSymbolAddress((void**)&wqt_l, g_wqt_l);
    cudaGetSymbolAddress((void**)&wkt_h, g_wkt_h); cudaGetSymbolAddress((void**)&wkt_l, g_wkt_l);
    cudaGetSymbolAddress((void**)&wvt_h, g_wvt_h); cudaGetSymbolAddress((void**)&wvt_l, g_wvt_l);
    cudaGetSymbolAddress((void**)&wot_h, g_wot_h); cudaGetSymbolAddress((void**)&wot_l, g_wot_l);
    cudaGetSymbolAddress((void**)&wgt_h, g_wgt_h); cudaGetSymbolAddress((void**)&wgt_l, g_wgt_l);
    cudaGetSymbolAddress((void**)&w1t_h, g_w1t_h); cudaGetSymbolAddress((void**)&w1t_l, g_w1t_l);
    cudaGetSymbolAddress((void**)&w2t_h, g_w2t_h); cudaGetSymbolAddress((void**)&w2t_l, g_w2t_l);
    cudaGetSymbolAddress((void**)&a_h, g_a_h);     cudaGetSymbolAddress((void**)&a_l, g_a_l);

    cudaFuncSetAttribute(attn2_kernel, cudaFuncAttributeMaxDynamicSharedMemorySize, ATTN2_SMEM);
    cudaFuncSetAttribute(hgemm<false>, cudaFuncAttributeMaxDynamicSharedMemorySize, HGEMM_SMEM);
    cudaFuncSetAttribute(hgemm<true>,  cudaFuncAttributeMaxDynamicSharedMemorySize, HGEMM_SMEM);

    // weight prep: transpose + hi/lo split (fp16)
    dim3 wt(32, 8);
    wsplit_kernel<<<dim3(D_ / 32, D_ / 32), wt>>>(wq, wqt_h, wqt_l, D_, D_);
    wsplit_kernel<<<dim3(D_ / 32, D_ / 32), wt>>>(wk, wkt_h, wkt_l, D_, D_);
    wsplit_kernel<<<dim3(D_ / 32, D_ / 32), wt>>>(wv, wvt_h, wvt_l, D_, D_);
    wsplit_kernel<<<dim3(D_ / 32, D_ / 32), wt>>>(wo, wot_h, wot_l, D_, D_);
    wsplit_kernel<<<dim3(FF_ / 32, D_ / 32), wt>>>(wg, wgt_h, wgt_l, D_, FF_);
    wsplit_kernel<<<dim3(FF_ / 32, D_ / 32), wt>>>(w1, w1t_h, w1t_l, D_, FF_);
    wsplit_kernel<<<dim3(D_ / 32, FF_ / 32), wt>>>(w2, w2t_h, w2t_l, FF_, D_);

    // xn = rmsnorm(x) -> a_h/a_l
    rmsnorm_split_kernel<<<S_, 256>>>(x, ln_w, a_h, a_l);

    // q,k,v projections
    dim3 gdd(S_ / 128, D_ / 128);
    hgemm<false><<<gdd, 256, HGEMM_SMEM>>>(S_, D_, D_, a_h, a_l, wqt_h, wqt_l, nullptr, q);
    hgemm<false><<<gdd, 256, HGEMM_SMEM>>>(S_, D_, D_, a_h, a_l, wkt_h, wkt_l, nullptr, k);
    hgemm<false><<<gdd, 256, HGEMM_SMEM>>>(S_, D_, D_, a_h, a_l, wvt_h, wvt_l, nullptr, v);

    // rope + attention (attention writes split fp16 O into a_h/a_l)
    rope_kernel<<<S_, 64>>>(q, k);
    attn2_kernel<<<dim3(S_ / 128, H_), 256, ATTN2_SMEM>>>(q, k, v, a_h, a_l);

    // x2 = attn @ wo + x
    hgemm<true><<<gdd, 256, HGEMM_SMEM>>>(S_, D_, D_, a_h, a_l, wot_h, wot_l, x, x2);

    // xn2 = rmsnorm(x2) -> a_h/a_l
    rmsnorm_split_kernel<<<S_, 256>>>(x2, ffln_w, a_h, a_l);

    // gate/up projections
    dim3 gdf(S_ / 128, FF_ / 128);
    hgemm<false><<<gdf, 256, HGEMM_SMEM>>>(S_, FF_, D_, a_h, a_l, wgt_h, wgt_l, nullptr, gate);
    hgemm<false><<<gdf, 256, HGEMM_SMEM>>>(S_, FF_, D_, a_h, a_l, w1t_h, w1t_l, nullptr, up);

    // h = silu(gate) * up -> a_h/a_l
    int n8 = (S_ * FF_) / 8;
    silu_split_kernel<<<(n8 + 255) / 256, 256>>>(gate, up, a_h, a_l, n8);

    // out = h @ w2 + x2
    hgemm<true><<<dim3(S_ / 128, D_ / 128), 256, HGEMM_SMEM>>>(S_, D_, FF_, a_h, a_l, w2t_h, w2t_l, x2, out);
}

// round 6
// speedup vs baseline: 1.9948x; 1.3715x over previous
#include <cuda_runtime.h>
#include <cuda_fp16.h>
#include <cstdint>
#include <math.h>

#define S_  2048
#define D_  4096
#define H_  32
#define HD_ 128
#define FF_ 11008

// ---------------- scratch (no allocations allowed) ----------------
__device__ float g_q   [(size_t)S_ * D_];
__device__ float g_k   [(size_t)S_ * D_];
__device__ float g_v   [(size_t)S_ * D_];
__device__ float g_x2  [(size_t)S_ * D_];
__device__ float g_gate[(size_t)S_ * FF_];
__device__ float g_up  [(size_t)S_ * FF_];

// transposed fp16 weights, layout [N, K] row-major (hi-only; 2-term scheme)
__device__ __half g_wqt[(size_t)D_ * D_];
__device__ __half g_wkt[(size_t)D_ * D_];
__device__ __half g_wvt[(size_t)D_ * D_];
__device__ __half g_wot[(size_t)D_ * D_];
__device__ __half g_wgt[(size_t)FF_ * D_];
__device__ __half g_w1t[(size_t)FF_ * D_];
__device__ __half g_w2t[(size_t)D_ * FF_];

// activation hi/lo split scratch (reused sequentially)
__device__ __half g_a_h[(size_t)S_ * FF_];
__device__ __half g_a_l[(size_t)S_ * FF_];

// ---------------- asm helpers ----------------
__device__ __forceinline__ uint32_t smem_to_u32(const void* p) {
    uint32_t a;
    asm("{ .reg .u64 t; cvta.to.shared.u64 t, %1; cvt.u32.u64 %0, t; }" : "=r"(a) : "l"(p));
    return a;
}
__device__ __forceinline__ void cp16(uint32_t saddr, const void* gaddr) {
    asm volatile("cp.async.cg.shared.global [%0], [%1], 16;" :: "r"(saddr), "l"(gaddr));
}
#define CP_COMMIT() asm volatile("cp.async.commit_group;" ::: "memory")
#define CP_WAIT(n)  asm volatile("cp.async.wait_group %0;" :: "n"(n) : "memory")

#define LDSM_X4(r0, r1, r2, r3, addr) \
    asm volatile("ldmatrix.sync.aligned.m8n8.x4.shared.b16 {%0,%1,%2,%3}, [%4];" \
        : "=r"(r0), "=r"(r1), "=r"(r2), "=r"(r3) : "r"(addr))
#define LDSM_X4_T(r0, r1, r2, r3, addr) \
    asm volatile("ldmatrix.sync.aligned.m8n8.x4.trans.shared.b16 {%0,%1,%2,%3}, [%4];" \
        : "=r"(r0), "=r"(r1), "=r"(r2), "=r"(r3) : "r"(addr))

#define MMA16816(d, a, b) \
    asm volatile("mma.sync.aligned.m16n8k16.row.col.f32.f16.f16.f32 " \
        "{%0,%1,%2,%3}, {%4,%5,%6,%7}, {%8,%9}, {%0,%1,%2,%3};" \
        : "+f"((d)[0]), "+f"((d)[1]), "+f"((d)[2]), "+f"((d)[3]) \
        : "r"((a)[0]), "r"((a)[1]), "r"((a)[2]), "r"((a)[3]), "r"((b)[0]), "r"((b)[1]))
#define MMA4(d, a0, a1, a2, a3, b0, b1) \
    asm volatile("mma.sync.aligned.m16n8k16.row.col.f32.f16.f16.f32 " \
        "{%0,%1,%2,%3}, {%4,%5,%6,%7}, {%8,%9}, {%0,%1,%2,%3};" \
        : "+f"((d)[0]), "+f"((d)[1]), "+f"((d)[2]), "+f"((d)[3]) \
        : "r"(a0), "r"(a1), "r"(a2), "r"(a3), "r"(b0), "r"(b1))

__device__ __forceinline__ uint32_t packh(__half a, __half b) {
    return ((uint32_t)__half_as_ushort(b) << 16) | __half_as_ushort(a);
}
// 8 floats -> 16B hi chunk + 16B lo chunk
__device__ __forceinline__ void cvt8(const float* v, uint4& hv, uint4& lv) {
    uint32_t hh[4], ll[4];
    #pragma unroll
    for (int j = 0; j < 4; j++) {
        float a = v[2 * j], b = v[2 * j + 1];
        __half ha = __float2half_rn(a), hb = __float2half_rn(b);
        __half la = __float2half_rn(a - __half2float(ha));
        __half lb = __float2half_rn(b - __half2float(hb));
        hh[j] = packh(ha, hb); ll[j] = packh(la, lb);
    }
    hv = make_uint4(hh[0], hh[1], hh[2], hh[3]);
    lv = make_uint4(ll[0], ll[1], ll[2], ll[3]);
}

// ---------------- weight transpose + fp16 round ----------------
__global__ __launch_bounds__(256) void wconv_kernel(
    const float* __restrict__ W, __half* __restrict__ Wh, int K, int N)
{
    __shared__ float t[32][33];
    int n0 = blockIdx.x * 32, k0 = blockIdx.y * 32;
    int tx = threadIdx.x, ty = threadIdx.y; // (32, 8)
    #pragma unroll
    for (int i = 0; i < 4; i++)
        t[ty + 8 * i][tx] = W[(size_t)(k0 + ty + 8 * i) * N + n0 + tx];
    __syncthreads();
    #pragma unroll
    for (int i = 0; i < 4; i++) {
        float v = t[tx][ty + 8 * i];
        Wh[(size_t)(n0 + ty + 8 * i) * K + k0 + tx] = __float2half_rn(v);
    }
}

// ---------------- HMMA GEMM v3: CTA 128x128, BK=64, 4-stage, 2-term ----------------
// C = (Ah + Al) @ Bh^T : A split fp16 activations, B fp16 weights.
#define STAGES 4
#define OPBYTES 16384                 // 128 rows x 64 f16 = 16KB
#define STAGE_BYTES (3 * OPBYTES)     // Ah | Al | Bh
#define HGEMM_SMEM (STAGES * STAGE_BYTES)

template <bool RESID>
__global__ __launch_bounds__(256) void hgemm(
    int M, int N, int K,
    const __half* __restrict__ Ah, const __half* __restrict__ Al,
    const __half* __restrict__ Bh,
    const float* __restrict__ Rsd, float* __restrict__ C)
{
    extern __shared__ __align__(1024) char smem[];
    const int tid  = threadIdx.x;
    const int wid  = tid >> 5;
    const int lane = tid & 31;
    const int m0 = blockIdx.x * 128;
    const int n0 = blockIdx.y * 128;
    const int nk = K >> 6;
    const uint32_t sbase = smem_to_u32(smem);

    const int wm = (wid & 3) * 32;   // warp M offset
    const int wn = (wid >> 2) * 64;  // warp N offset

    const __half* Abase_h = Ah + (size_t)m0 * K;
    const __half* Abase_l = Al + (size_t)m0 * K;
    const __half* Bbase   = Bh + (size_t)n0 * K;

    // per-thread load coords (4 chunks of 16B per operand)
    int lrow[4], lcc[4];
    uint32_t lsoff[4];
    #pragma unroll
    for (int t = 0; t < 4; t++) {
        int c = tid + t * 256;
        lrow[t] = c >> 3;
        lcc[t]  = c & 7;
        lsoff[t] = lrow[t] * 128 + (((lcc[t] ^ (lrow[t] & 7))) << 4);
    }

    #define ISSUE(s, kt) do { \
        uint32_t sb_ = sbase + (s) * STAGE_BYTES; \
        size_t kofs_ = (size_t)(kt) << 6; \
        _Pragma("unroll") \
        for (int t = 0; t < 4; t++) { \
            size_t go_ = (size_t)lrow[t] * K + kofs_ + lcc[t] * 8; \
            uint32_t so_ = sb_ + lsoff[t]; \
            cp16(so_,               Abase_h + go_); \
            cp16(so_ + OPBYTES,     Abase_l + go_); \
            cp16(so_ + 2 * OPBYTES, Bbase   + go_); \
        } \
    } while (0)

    float acc[2][8][4] = {};

    #pragma unroll
    for (int s = 0; s < STAGES - 1; s++) { ISSUE(s, s); CP_COMMIT(); }

    const int mat = lane >> 3, rin = lane & 7;

    for (int i = 0; i < nk; i++) {
        CP_WAIT(STAGES - 2);
        __syncthreads();
        if (i + STAGES - 1 < nk) { ISSUE((i + STAGES - 1) % STAGES, i + STAGES - 1); }
        CP_COMMIT();

        uint32_t stg = sbase + (i % STAGES) * STAGE_BYTES;
        #pragma unroll
        for (int ks = 0; ks < 4; ks++) {
            int ks2 = ks << 1;
            uint32_t fa_h[2][4], fa_l[2][4], fb[8][2];
            #pragma unroll
            for (int mt = 0; mt < 2; mt++) {
                int m = wm + mt * 16 + ((mat & 1) << 3) + rin;
                uint32_t ad = stg + m * 128 + (((ks2 + (mat >> 1)) ^ (m & 7)) << 4);
                LDSM_X4(fa_h[mt][0], fa_h[mt][1], fa_h[mt][2], fa_h[mt][3], ad);
                LDSM_X4(fa_l[mt][0], fa_l[mt][1], fa_l[mt][2], fa_l[mt][3], ad + OPBYTES);
            }
            #pragma unroll
            for (int p = 0; p < 4; p++) {
                int n = wn + p * 16 + ((mat >> 1) << 3) + rin;
                uint32_t bd = stg + 2 * OPBYTES + n * 128 + (((ks2 + (mat & 1)) ^ (n & 7)) << 4);
                uint32_t r0, r1, r2, r3;
                LDSM_X4(r0, r1, r2, r3, bd);
                fb[p * 2][0] = r0; fb[p * 2][1] = r1;
                fb[p * 2 + 1][0] = r2; fb[p * 2 + 1][1] = r3;
            }
            #pragma unroll
            for (int mt = 0; mt < 2; mt++)
                #pragma unroll
                for (int nt = 0; nt < 8; nt++) {
                    MMA16816(acc[mt][nt], fa_h[mt], fb[nt]);
                    MMA16816(acc[mt][nt], fa_l[mt], fb[nt]);
                }
        }
        __syncthreads();
    }
    #undef ISSUE

    int qr = lane >> 2, qc = (lane & 3) << 1;
    #pragma unroll
    for (int mt = 0; mt < 2; mt++) {
        #pragma unroll
        for (int nt = 0; nt < 8; nt++) {
            int r0 = m0 + wm + mt * 16 + qr;
            int cc = n0 + wn + nt * 8 + qc;
            float2 v0 = make_float2(acc[mt][nt][0], acc[mt][nt][1]);
            float2 v1 = make_float2(acc[mt][nt][2], acc[mt][nt][3]);
            if (RESID) {
                float2 a = *(const float2*)(Rsd + (size_t)r0 * N + cc);
                float2 b = *(const float2*)(Rsd + (size_t)(r0 + 8) * N + cc);
                v0.x += a.x; v0.y += a.y; v1.x += b.x; v1.y += b.y;
            }
            *(float2*)(C + (size_t)r0 * N + cc)       = v0;
            *(float2*)(C + (size_t)(r0 + 8) * N + cc) = v1;
        }
    }
}

// ---------------- RMSNorm with fused fp16 hi/lo split output ----------------
__global__ __launch_bounds__(256) void rmsnorm_split_kernel(
    const float* __restrict__ x, const float* __restrict__ w,
    __half* __restrict__ oh, __half* __restrict__ ol)
{
    int row = blockIdx.x;
    const float4* xr = (const float4*)(x + (size_t)row * D_);
    float ss = 0.f;
    #pragma unroll 4
    for (int i = threadIdx.x; i < D_ / 4; i += 256) {
        float4 v = xr[i];
        ss += v.x * v.x + v.y * v.y + v.z * v.z + v.w * v.w;
    }
    __shared__ float red[8];
    #pragma unroll
    for (int o = 16; o; o >>= 1) ss += __shfl_xor_sync(0xffffffffu, ss, o);
    if ((threadIdx.x & 31) == 0) red[threadIdx.x >> 5] = ss;
    __syncthreads();
    if (threadIdx.x == 0) {
        float t = 0.f;
        #pragma unroll
        for (int i = 0; i < 8; i++) t += red[i];
        red[0] = rsqrtf(t / (float)D_ + 1e-5f);
    }
    __syncthreads();
    float inv = red[0];
    const float4* wr = (const float4*)w;
    for (int i = threadIdx.x; i < D_ / 8; i += 256) {
        float vv[8];
        float4 a = xr[2 * i], b = xr[2 * i + 1];
        float4 wa = wr[2 * i], wb = wr[2 * i + 1];
        vv[0] = a.x * inv * wa.x; vv[1] = a.y * inv * wa.y;
        vv[2] = a.z * inv * wa.z; vv[3] = a.w * inv * wa.w;
        vv[4] = b.x * inv * wb.x; vv[5] = b.y * inv * wb.y;
        vv[6] = b.z * inv * wb.z; vv[7] = b.w * inv * wb.w;
        uint4 hv, lv;
        cvt8(vv, hv, lv);
        ((uint4*)(oh + (size_t)row * D_))[i] = hv;
        ((uint4*)(ol + (size_t)row * D_))[i] = lv;
    }
}

// ---------------- RoPE (q and k in place, fp32) ----------------
__global__ void rope_kernel(float* __restrict__ q, float* __restrict__ k)
{
    int s = blockIdx.x;
    int j = threadIdx.x;   // 0..63 pair index
    float inv = (float)exp((double)j * -0.14391156831212787);
    float ang = (float)s * inv;
    float sn, cs;
    sincosf(ang, &sn, &cs);
    #pragma unroll 4
    for (int h = 0; h < H_; h++) {
        size_t base = ((size_t)s * H_ + h) * HD_ + 2 * j;
        float q1 = q[base], q2 = q[base + 1];
        q[base]     = q1 * cs - q2 * sn;
        q[base + 1] = q1 * sn + q2 * cs;
        float k1 = k[base], k2 = k[base + 1];
        k[base]     = k1 * cs - k2 * sn;
        k[base + 1] = k1 * sn + k2 * cs;
    }
}

// ---------------- HMMA flash attention ----------------
// BQ=128, BK=64, 8 warps x 16 q-rows, fp16 hi/lo 3-term, fp32 softmax.
#define AQH 0
#define AQL 32768
#define AKH 65536
#define AKL 81920
#define AVH 98304
#define AVL 114688
#define ATTN2_SMEM 131072

__global__ __launch_bounds__(256, 1) void attn2_kernel(
    const float* __restrict__ Q, const float* __restrict__ Kg,
    const float* __restrict__ Vg, __half* __restrict__ Oh, __half* __restrict__ Ol)
{
    extern __shared__ __align__(1024) char sm2[];
    const uint32_t sb = smem_to_u32(sm2);
    const int tid = threadIdx.x, wid = tid >> 5, lane = tid & 31;
    const int h = blockIdx.y;
    const int bq = gridDim.x - 1 - blockIdx.x;   // long CTAs first
    const int q0 = bq * 128;
    const int mat = lane >> 3, rin = lane & 7;
    const float scale = 0.08838834764831845f;

    // load + scale + split Q tile (128 x 128)
    #pragma unroll
    for (int i = 0; i < 8; i++) {
        int idx = tid + i * 256;
        int row = idx >> 4, cc = idx & 15;
        const float* gp = Q + (size_t)(q0 + row) * D_ + h * HD_ + cc * 8;
        float vv[8];
        float4 a = *(const float4*)gp, b = *(const float4*)(gp + 4);
        vv[0] = a.x * scale; vv[1] = a.y * scale; vv[2] = a.z * scale; vv[3] = a.w * scale;
        vv[4] = b.x * scale; vv[5] = b.y * scale; vv[6] = b.z * scale; vv[7] = b.w * scale;
        uint4 hv, lv;
        cvt8(vv, hv, lv);
        uint32_t off = row * 256 + ((cc ^ (row & 7)) << 4);
        *(uint4*)(sm2 + AQH + off) = hv;
        *(uint4*)(sm2 + AQL + off) = lv;
    }

    float m0 = -1e30f, m1 = -1e30f, l0 = 0.f, l1 = 0.f;
    float oacc[16][4] = {};
    const int g0r = q0 + wid * 16 + (lane >> 2);
    const int g1r = g0r + 8;
    const int nk = q0 / 64 + 2;
    __syncthreads();

    for (int kt = 0; kt < nk; kt++) {
        int k0 = kt * 64;
        // load + split K, V tiles (64 x 128 each)
        #pragma unroll
        for (int i = 0; i < 4; i++) {
            int idx = tid + i * 256;
            int row = idx >> 4, cc = idx & 15;
            uint32_t off = row * 256 + ((cc ^ (row & 7)) << 4);
            const float* kp = Kg + (size_t)(k0 + row) * D_ + h * HD_ + cc * 8;
            float vv[8];
            float4 a = *(const float4*)kp, b = *(const float4*)(kp + 4);
            vv[0] = a.x; vv[1] = a.y; vv[2] = a.z; vv[3] = a.w;
            vv[4] = b.x; vv[5] = b.y; vv[6] = b.z; vv[7] = b.w;
            uint4 hv, lv;
            cvt8(vv, hv, lv);
            *(uint4*)(sm2 + AKH + off) = hv;
            *(uint4*)(sm2 + AKL + off) = lv;
            const float* vp = Vg + (size_t)(k0 + row) * D_ + h * HD_ + cc * 8;
            a = *(const float4*)vp; b = *(const float4*)(vp + 4);
            vv[0] = a.x; vv[1] = a.y; vv[2] = a.z; vv[3] = a.w;
            vv[4] = b.x; vv[5] = b.y; vv[6] = b.z; vv[7] = b.w;
            cvt8(vv, hv, lv);
            *(uint4*)(sm2 + AVH + off) = hv;
            *(uint4*)(sm2 + AVL + off) = lv;
        }
        __syncthreads();

        // S = Q K^T (this warp: 16x64)
        float sacc[8][4] = {};
        #pragma unroll
        for (int kk = 0; kk < 8; kk++) {
            int kk2 = kk << 1;
            int m = wid * 16 + ((mat & 1) << 3) + rin;
            uint32_t ad = sb + AQH + m * 256 + (((kk2 + (mat >> 1)) ^ (m & 7)) << 4);
            uint32_t qa_h[4], qa_l[4];
            LDSM_X4(qa_h[0], qa_h[1], qa_h[2], qa_h[3], ad);
            LDSM_X4(qa_l[0], qa_l[1], qa_l[2], qa_l[3], ad + (AQL - AQH));
            #pragma unroll
            for (int nt = 0; nt < 4; nt++) {
                int n = nt * 16 + ((mat >> 1) << 3) + rin;
                uint32_t bd = sb + AKH + n * 256 + (((kk2 + (mat & 1)) ^ (n & 7)) << 4);
                uint32_t b0, b1, b2, b3, c0, c1, c2, c3;
                LDSM_X4(b0, b1, b2, b3, bd);
                LDSM_X4(c0, c1, c2, c3, bd + (AKL - AKH));
                MMA4(sacc[2 * nt],     qa_h[0], qa_h[1], qa_h[2], qa_h[3], b0, b1);
                MMA4(sacc[2 * nt],     qa_h[0], qa_h[1], qa_h[2], qa_h[3], c0, c1);
                MMA4(sacc[2 * nt],     qa_l[0], qa_l[1], qa_l[2], qa_l[3], b0, b1);
                MMA4(sacc[2 * nt + 1], qa_h[0], qa_h[1], qa_h[2], qa_h[3], b2, b3);
                MMA4(sacc[2 * nt + 1], qa_h[0], qa_h[1], qa_h[2], qa_h[3], c2, c3);
                MMA4(sacc[2 * nt + 1], qa_l[0], qa_l[1], qa_l[2], qa_l[3], b2, b3);
            }
        }

        // causal mask
        if (k0 + 63 > g0r) {
            #pragma unroll
            for (int nt = 0; nt < 8; nt++) {
                int c0 = k0 + nt * 8 + ((lane & 3) << 1);
                if (c0     > g0r) sacc[nt][0] = -1e30f;
                if (c0 + 1 > g0r) sacc[nt][1] = -1e30f;
                if (c0     > g1r) sacc[nt][2] = -1e30f;
                if (c0 + 1 > g1r) sacc[nt][3] = -1e30f;
            }
        }

        // online softmax
        float mx0 = m0, mx1 = m1;
        #pragma unroll
        for (int nt = 0; nt < 8; nt++) {
            mx0 = fmaxf(mx0, fmaxf(sacc[nt][0], sacc[nt][1]));
            mx1 = fmaxf(mx1, fmaxf(sacc[nt][2], sacc[nt][3]));
        }
        mx0 = fmaxf(mx0, __shfl_xor_sync(0xffffffffu, mx0, 1));
        mx0 = fmaxf(mx0, __shfl_xor_sync(0xffffffffu, mx0, 2));
        mx1 = fmaxf(mx1, __shfl_xor_sync(0xffffffffu, mx1, 1));
        mx1 = fmaxf(mx1, __shfl_xor_sync(0xffffffffu, mx1, 2));
        float al0 = __expf(m0 - mx0), al1 = __expf(m1 - mx1);
        m0 = mx0; m1 = mx1;
        float rs0 = 0.f, rs1 = 0.f;
        uint32_t ph0[8], ph1[8], pl0[8], pl1[8];
        #pragma unroll
        for (int nt = 0; nt < 8; nt++) {
            float p0 = __expf(sacc[nt][0] - mx0);
            float p1 = __expf(sacc[nt][1] - mx0);
            float p2 = __expf(sacc[nt][2] - mx1);
            float p3 = __expf(sacc[nt][3] - mx1);
            rs0 += p0 + p1; rs1 += p2 + p3;
            __half h0 = __float2half_rn(p0), h1 = __float2half_rn(p1);
            __half h2 = __float2half_rn(p2), h3 = __float2half_rn(p3);
            ph0[nt] = packh(h0, h1); ph1[nt] = packh(h2, h3);
            pl0[nt] = packh(__float2half_rn(p0 - __half2float(h0)),
                            __float2half_rn(p1 - __half2float(h1)));
            pl1[nt] = packh(__float2half_rn(p2 - __half2float(h2)),
                            __float2half_rn(p3 - __half2float(h3)));
        }
        rs0 += __shfl_xor_sync(0xffffffffu, rs0, 1);
        rs0 += __shfl_xor_sync(0xffffffffu, rs0, 2);
        rs1 += __shfl_xor_sync(0xffffffffu, rs1, 1);
        rs1 += __shfl_xor_sync(0xffffffffu, rs1, 2);
        l0 = l0 * al0 + rs0;
        l1 = l1 * al1 + rs1;
        #pragma unroll
        for (int t = 0; t < 16; t++) {
            oacc[t][0] *= al0; oacc[t][1] *= al0;
            oacc[t][2] *= al1; oacc[t][3] *= al1;
        }

        // O += P @ V
        #pragma unroll
        for (int kk = 0; kk < 4; kk++) {
            uint32_t a0 = ph0[2 * kk], a1 = ph1[2 * kk], a2 = ph0[2 * kk + 1], a3 = ph1[2 * kk + 1];
            uint32_t e0 = pl0[2 * kk], e1 = pl1[2 * kk], e2 = pl0[2 * kk + 1], e3 = pl1[2 * kk + 1];
            #pragma unroll
            for (int ntp = 0; ntp < 8; ntp++) {
                int vrow = kk * 16 + rin + ((mat >> 1) << 3);
                int vch  = 2 * ntp + (mat & 1);
                uint32_t vd = sb + AVH + vrow * 256 + ((vch ^ (vrow & 7)) << 4);
                uint32_t r0, r1, r2, r3, s0, s1, s2, s3;
                LDSM_X4_T(r0, r1, r2, r3, vd);
                LDSM_X4_T(s0, s1, s2, s3, vd + (AVL - AVH));
                MMA4(oacc[2 * ntp],     a0, a1, a2, a3, r0, r2);
                MMA4(oacc[2 * ntp],     a0, a1, a2, a3, s0, s2);
                MMA4(oacc[2 * ntp],     e0, e1, e2, e3, r0, r2);
                MMA4(oacc[2 * ntp + 1], a0, a1, a2, a3, r1, r3);
                MMA4(oacc[2 * ntp + 1], a0, a1, a2, a3, s1, s3);
                MMA4(oacc[2 * ntp + 1], e0, e1, e2, e3, r1, r3);
            }
        }
        __syncthreads();
    }

    // write O (split to h/l fp16)
    float i0 = 1.f / l0, i1 = 1.f / l1;
    #pragma unroll
    for (int t = 0; t < 16; t++) {
        int col = h * HD_ + t * 8 + ((lane & 3) << 1);
        float v0 = oacc[t][0] * i0, v1 = oacc[t][1] * i0;
        float v2 = oacc[t][2] * i1, v3 = oacc[t][3] * i1;
        __half h0 = __float2half_rn(v0), h1 = __float2half_rn(v1);
        __half h2 = __float2half_rn(v2), h3 = __float2half_rn(v3);
        *reinterpret_cast<uint32_t*>(Oh + (size_t)g0r * D_ + col) = packh(h0, h1);
        *reinterpret_cast<uint32_t*>(Oh + (size_t)g1r * D_ + col) = packh(h2, h3);
        *reinterpret_cast<uint32_t*>(Ol + (size_t)g0r * D_ + col) =
            packh(__float2half_rn(v0 - __half2float(h0)), __float2half_rn(v1 - __half2float(h1)));
        *reinterpret_cast<uint32_t*>(Ol + (size_t)g1r * D_ + col) =
            packh(__float2half_rn(v2 - __half2float(h2)), __float2half_rn(v3 - __half2float(h3)));
    }
}

// ---------------- SiLU(gate) * up with fused split output ----------------
__global__ void silu_split_kernel(const float* __restrict__ g, const float* __restrict__ u,
                                  __half* __restrict__ oh, __half* __restrict__ ol, int n8)
{
    int i = blockIdx.x * blockDim.x + threadIdx.x;
    if (i < n8) {
        float4 g0 = ((const float4*)g)[2 * i], g1 = ((const float4*)g)[2 * i + 1];
        float4 u0 = ((const float4*)u)[2 * i], u1 = ((const float4*)u)[2 * i + 1];
        float vv[8];
        vv[0] = g0.x / (1.f + __expf(-g0.x)) * u0.x;
        vv[1] = g0.y / (1.f + __expf(-g0.y)) * u0.y;
        vv[2] = g0.z / (1.f + __expf(-g0.z)) * u0.z;
        vv[3] = g0.w / (1.f + __expf(-g0.w)) * u0.w;
        vv[4] = g1.x / (1.f + __expf(-g1.x)) * u1.x;
        vv[5] = g1.y / (1.f + __expf(-g1.y)) * u1.y;
        vv[6] = g1.z / (1.f + __expf(-g1.z)) * u1.z;
        vv[7] = g1.w / (1.f + __expf(-g1.w)) * u1.w;
        uint4 hv, lv;
        cvt8(vv, hv, lv);
        ((uint4*)oh)[i] = hv;
        ((uint4*)ol)[i] = lv;
    }
}

// ---------------- launch ----------------
extern "C" void kernel_launch(void* const* d_in, const int* in_sizes, int n_in,
                              void* d_out, int out_size)
{
    const float* x      = (const float*)d_in[0];
    const float* ln_w   = (const float*)d_in[1];
    const float* ffln_w = (const float*)d_in[2];
    const float* wq     = (const float*)d_in[3];
    const float* wk     = (const float*)d_in[4];
    const float* wv     = (const float*)d_in[5];
    const float* wo     = (const float*)d_in[6];
    const float* wg     = (const float*)d_in[7];
    const float* w1     = (const float*)d_in[8];
    const float* w2     = (const float*)d_in[9];
    float* out = (float*)d_out;

    float *q, *k, *v, *x2, *gate, *up;
    cudaGetSymbolAddress((void**)&q,    g_q);
    cudaGetSymbolAddress((void**)&k,    g_k);
    cudaGetSymbolAddress((void**)&v,    g_v);
    cudaGetSymbolAddress((void**)&x2,   g_x2);
    cudaGetSymbolAddress((void**)&gate, g_gate);
    cudaGetSymbolAddress((void**)&up,   g_up);

    __half *wqt, *wkt, *wvt, *wot, *wgt, *w1t, *w2t, *a_h, *a_l;
    cudaGetSymbolAddress((void**)&wqt, g_wqt);
    cudaGetSymbolAddress((void**)&wkt, g_wkt);
    cudaGetSymbolAddress((void**)&wvt, g_wvt);
    cudaGetSymbolAddress((void**)&wot, g_wot);
    cudaGetSymbolAddress((void**)&wgt, g_wgt);
    cudaGetSymbolAddress((void**)&w1t, g_w1t);
    cudaGetSymbolAddress((void**)&w2t, g_w2t);
    cudaGetSymbolAddress((void**)&a_h, g_a_h);
    cudaGetSymbolAddress((void**)&a_l, g_a_l);

    cudaFuncSetAttribute(attn2_kernel, cudaFuncAttributeMaxDynamicSharedMemorySize, ATTN2_SMEM);
    cudaFuncSetAttribute(hgemm<false>, cudaFuncAttributeMaxDynamicSharedMemorySize, HGEMM_SMEM);
    cudaFuncSetAttribute(hgemm<true>,  cudaFuncAttributeMaxDynamicSharedMemorySize, HGEMM_SMEM);

    // weight prep: transpose + fp16 round
    dim3 wt(32, 8);
    wconv_kernel<<<dim3(D_ / 32, D_ / 32), wt>>>(wq, wqt, D_, D_);
    wconv_kernel<<<dim3(D_ / 32, D_ / 32), wt>>>(wk, wkt, D_, D_);
    wconv_kernel<<<dim3(D_ / 32, D_ / 32), wt>>>(wv, wvt, D_, D_);
    wconv_kernel<<<dim3(D_ / 32, D_ / 32), wt>>>(wo, wot, D_, D_);
    wconv_kernel<<<dim3(FF_ / 32, D_ / 32), wt>>>(wg, wgt, D_, FF_);
    wconv_kernel<<<dim3(FF_ / 32, D_ / 32), wt>>>(w1, w1t, D_, FF_);
    wconv_kernel<<<dim3(D_ / 32, FF_ / 32), wt>>>(w2, w2t, FF_, D_);

    // xn = rmsnorm(x) -> a_h/a_l
    rmsnorm_split_kernel<<<S_, 256>>>(x, ln_w, a_h, a_l);

    // q,k,v projections
    dim3 gdd(S_ / 128, D_ / 128);
    hgemm<false><<<gdd, 256, HGEMM_SMEM>>>(S_, D_, D_, a_h, a_l, wqt, nullptr, q);
    hgemm<false><<<gdd, 256, HGEMM_SMEM>>>(S_, D_, D_, a_h, a_l, wkt, nullptr, k);
    hgemm<false><<<gdd, 256, HGEMM_SMEM>>>(S_, D_, D_, a_h, a_l, wvt, nullptr, v);

    // rope + attention (attention writes split fp16 O into a_h/a_l)
    rope_kernel<<<S_, 64>>>(q, k);
    attn2_kernel<<<dim3(S_ / 128, H_), 256, ATTN2_SMEM>>>(q, k, v, a_h, a_l);

    // x2 = attn @ wo + x
    hgemm<true><<<gdd, 256, HGEMM_SMEM>>>(S_, D_, D_, a_h, a_l, wot, x, x2);

    // xn2 = rmsnorm(x2) -> a_h/a_l
    rmsnorm_split_kernel<<<S_, 256>>>(x2, ffln_w, a_h, a_l);

    // gate/up projections
    dim3 gdf(S_ / 128, FF_ / 128);
    hgemm<false><<<gdf, 256, HGEMM_SMEM>>>(S_, FF_, D_, a_h, a_l, wgt, nullptr, gate);
    hgemm<false><<<gdf, 256, HGEMM_SMEM>>>(S_, FF_, D_, a_h, a_l, w1t, nullptr, up);

    // h = silu(gate) * up -> a_h/a_l
    int n8 = (S_ * FF_) / 8;
    silu_split_kernel<<<(n8 + 255) / 256, 256>>>(gate, up, a_h, a_l, n8);

    // out = h @ w2 + x2
    hgemm<true><<<dim3(S_ / 128, D_ / 128), 256, HGEMM_SMEM>>>(S_, D_, FF_, a_h, a_l, w2t, x2, out);
}

// round 7
// speedup vs baseline: 3.1138x; 1.5610x over previous
#include <cuda_runtime.h>
#include <cuda_fp16.h>
#include <cstdint>
#include <math.h>

#define S_  2048
#define D_  4096
#define H_  32
#define HD_ 128
#define FF_ 11008

// ---------------- scratch (no allocations allowed) ----------------
__device__ float g_q   [(size_t)S_ * D_];
__device__ float g_k   [(size_t)S_ * D_];
__device__ float g_v   [(size_t)S_ * D_];
__device__ float g_x2  [(size_t)S_ * D_];
__device__ float g_gate[(size_t)S_ * FF_];
__device__ float g_up  [(size_t)S_ * FF_];

// transposed fp16 weights, layout [N, K] row-major
__device__ __half g_wqt[(size_t)D_ * D_];
__device__ __half g_wkt[(size_t)D_ * D_];
__device__ __half g_wvt[(size_t)D_ * D_];
__device__ __half g_wot[(size_t)D_ * D_];
__device__ __half g_wgt[(size_t)FF_ * D_];
__device__ __half g_w1t[(size_t)FF_ * D_];
__device__ __half g_w2t[(size_t)D_ * FF_];

// fp16 activation scratch (reused sequentially)
__device__ __half g_a_h[(size_t)S_ * FF_];

// ---------------- asm helpers ----------------
__device__ __forceinline__ uint32_t smem_to_u32(const void* p) {
    uint32_t a;
    asm("{ .reg .u64 t; cvta.to.shared.u64 t, %1; cvt.u32.u64 %0, t; }" : "=r"(a) : "l"(p));
    return a;
}
__device__ __forceinline__ void cp16(uint32_t saddr, const void* gaddr) {
    asm volatile("cp.async.cg.shared.global [%0], [%1], 16;" :: "r"(saddr), "l"(gaddr));
}
#define CP_COMMIT() asm volatile("cp.async.commit_group;" ::: "memory")
#define CP_WAIT(n)  asm volatile("cp.async.wait_group %0;" :: "n"(n) : "memory")

#define LDSM_X4(r0, r1, r2, r3, addr) \
    asm volatile("ldmatrix.sync.aligned.m8n8.x4.shared.b16 {%0,%1,%2,%3}, [%4];" \
        : "=r"(r0), "=r"(r1), "=r"(r2), "=r"(r3) : "r"(addr))
#define LDSM_X4_T(r0, r1, r2, r3, addr) \
    asm volatile("ldmatrix.sync.aligned.m8n8.x4.trans.shared.b16 {%0,%1,%2,%3}, [%4];" \
        : "=r"(r0), "=r"(r1), "=r"(r2), "=r"(r3) : "r"(addr))

#define MMA16816(d, a, b) \
    asm volatile("mma.sync.aligned.m16n8k16.row.col.f32.f16.f16.f32 " \
        "{%0,%1,%2,%3}, {%4,%5,%6,%7}, {%8,%9}, {%0,%1,%2,%3};" \
        : "+f"((d)[0]), "+f"((d)[1]), "+f"((d)[2]), "+f"((d)[3]) \
        : "r"((a)[0]), "r"((a)[1]), "r"((a)[2]), "r"((a)[3]), "r"((b)[0]), "r"((b)[1]))
#define MMA4(d, a0, a1, a2, a3, b0, b1) \
    asm volatile("mma.sync.aligned.m16n8k16.row.col.f32.f16.f16.f32 " \
        "{%0,%1,%2,%3}, {%4,%5,%6,%7}, {%8,%9}, {%0,%1,%2,%3};" \
        : "+f"((d)[0]), "+f"((d)[1]), "+f"((d)[2]), "+f"((d)[3]) \
        : "r"(a0), "r"(a1), "r"(a2), "r"(a3), "r"(b0), "r"(b1))

__device__ __forceinline__ uint32_t packh(__half a, __half b) {
    return ((uint32_t)__half_as_ushort(b) << 16) | __half_as_ushort(a);
}
// 8 floats -> 16B hi chunk + 16B lo chunk (used by attention)
__device__ __forceinline__ void cvt8(const float* v, uint4& hv, uint4& lv) {
    uint32_t hh[4], ll[4];
    #pragma unroll
    for (int j = 0; j < 4; j++) {
        float a = v[2 * j], b = v[2 * j + 1];
        __half ha = __float2half_rn(a), hb = __float2half_rn(b);
        __half la = __float2half_rn(a - __half2float(ha));
        __half lb = __float2half_rn(b - __half2float(hb));
        hh[j] = packh(ha, hb); ll[j] = packh(la, lb);
    }
    hv = make_uint4(hh[0], hh[1], hh[2], hh[3]);
    lv = make_uint4(ll[0], ll[1], ll[2], ll[3]);
}
// 8 floats -> 16B fp16 chunk
__device__ __forceinline__ uint4 cvt8h(const float* v) {
    uint32_t hh[4];
    #pragma unroll
    for (int j = 0; j < 4; j++)
        hh[j] = packh(__float2half_rn(v[2 * j]), __float2half_rn(v[2 * j + 1]));
    return make_uint4(hh[0], hh[1], hh[2], hh[3]);
}

// ---------------- weight transpose + fp16 round ----------------
__global__ __launch_bounds__(256) void wconv_kernel(
    const float* __restrict__ W, __half* __restrict__ Wh, int K, int N)
{
    __shared__ float t[32][33];
    int n0 = blockIdx.x * 32, k0 = blockIdx.y * 32;
    int tx = threadIdx.x, ty = threadIdx.y; // (32, 8)
    #pragma unroll
    for (int i = 0; i < 4; i++)
        t[ty + 8 * i][tx] = W[(size_t)(k0 + ty + 8 * i) * N + n0 + tx];
    __syncthreads();
    #pragma unroll
    for (int i = 0; i < 4; i++) {
        float v = t[tx][ty + 8 * i];
        Wh[(size_t)(n0 + ty + 8 * i) * K + k0 + tx] = __float2half_rn(v);
    }
}

// ---------------- HMMA GEMM v4: plain fp16, CTA 128x128, BK=64, 5-stage ----------------
#define STAGES 5
#define OPBYTES 16384                 // 128 rows x 64 f16 = 16KB
#define STAGE_BYTES (2 * OPBYTES)     // A | B
#define HGEMM_SMEM (STAGES * STAGE_BYTES)

template <bool RESID>
__global__ __launch_bounds__(256) void hgemm(
    int M, int N, int K,
    const __half* __restrict__ A, const __half* __restrict__ B,
    const float* __restrict__ Rsd, float* __restrict__ C)
{
    extern __shared__ __align__(1024) char smem[];
    const int tid  = threadIdx.x;
    const int wid  = tid >> 5;
    const int lane = tid & 31;
    const int m0 = blockIdx.x * 128;
    const int n0 = blockIdx.y * 128;
    const int nk = K >> 6;
    const uint32_t sbase = smem_to_u32(smem);

    const int wm = (wid & 3) * 32;   // warp M offset
    const int wn = (wid >> 2) * 64;  // warp N offset

    const __half* Abase = A + (size_t)m0 * K;
    const __half* Bbase = B + (size_t)n0 * K;

    // per-thread load coords (4 chunks of 16B per operand)
    int lrow[4], lcc[4];
    uint32_t lsoff[4];
    #pragma unroll
    for (int t = 0; t < 4; t++) {
        int c = tid + t * 256;
        lrow[t] = c >> 3;
        lcc[t]  = c & 7;
        lsoff[t] = lrow[t] * 128 + (((lcc[t] ^ (lrow[t] & 7))) << 4);
    }

    #define ISSUE(s, kt) do { \
        uint32_t sb_ = sbase + (s) * STAGE_BYTES; \
        size_t kofs_ = (size_t)(kt) << 6; \
        _Pragma("unroll") \
        for (int t = 0; t < 4; t++) { \
            size_t go_ = (size_t)lrow[t] * K + kofs_ + lcc[t] * 8; \
            uint32_t so_ = sb_ + lsoff[t]; \
            cp16(so_,           Abase + go_); \
            cp16(so_ + OPBYTES, Bbase + go_); \
        } \
    } while (0)

    float acc[2][8][4] = {};

    #pragma unroll
    for (int s = 0; s < STAGES - 1; s++) { ISSUE(s, s); CP_COMMIT(); }

    const int mat = lane >> 3, rin = lane & 7;

    for (int i = 0; i < nk; i++) {
        CP_WAIT(STAGES - 2);
        __syncthreads();
        if (i + STAGES - 1 < nk) { ISSUE((i + STAGES - 1) % STAGES, i + STAGES - 1); }
        CP_COMMIT();

        uint32_t stg = sbase + (i % STAGES) * STAGE_BYTES;
        #pragma unroll
        for (int ks = 0; ks < 4; ks++) {
            int ks2 = ks << 1;
            uint32_t fa[2][4], fb[8][2];
            #pragma unroll
            for (int mt = 0; mt < 2; mt++) {
                int m = wm + mt * 16 + ((mat & 1) << 3) + rin;
                uint32_t ad = stg + m * 128 + (((ks2 + (mat >> 1)) ^ (m & 7)) << 4);
                LDSM_X4(fa[mt][0], fa[mt][1], fa[mt][2], fa[mt][3], ad);
            }
            #pragma unroll
            for (int p = 0; p < 4; p++) {
                int n = wn + p * 16 + ((mat >> 1) << 3) + rin;
                uint32_t bd = stg + OPBYTES + n * 128 + (((ks2 + (mat & 1)) ^ (n & 7)) << 4);
                uint32_t r0, r1, r2, r3;
                LDSM_X4(r0, r1, r2, r3, bd);
                fb[p * 2][0] = r0; fb[p * 2][1] = r1;
                fb[p * 2 + 1][0] = r2; fb[p * 2 + 1][1] = r3;
            }
            #pragma unroll
            for (int mt = 0; mt < 2; mt++)
                #pragma unroll
                for (int nt = 0; nt < 8; nt++)
                    MMA16816(acc[mt][nt], fa[mt], fb[nt]);
        }
        __syncthreads();
    }
    #undef ISSUE

    int qr = lane >> 2, qc = (lane & 3) << 1;
    #pragma unroll
    for (int mt = 0; mt < 2; mt++) {
        #pragma unroll
        for (int nt = 0; nt < 8; nt++) {
            int r0 = m0 + wm + mt * 16 + qr;
            int cc = n0 + wn + nt * 8 + qc;
            float2 v0 = make_float2(acc[mt][nt][0], acc[mt][nt][1]);
            float2 v1 = make_float2(acc[mt][nt][2], acc[mt][nt][3]);
            if (RESID) {
                float2 a = *(const float2*)(Rsd + (size_t)r0 * N + cc);
                float2 b = *(const float2*)(Rsd + (size_t)(r0 + 8) * N + cc);
                v0.x += a.x; v0.y += a.y; v1.x += b.x; v1.y += b.y;
            }
            *(float2*)(C + (size_t)r0 * N + cc)       = v0;
            *(float2*)(C + (size_t)(r0 + 8) * N + cc) = v1;
        }
    }
}

// ---------------- RMSNorm with fused fp16 output ----------------
__global__ __launch_bounds__(256) void rmsnorm_h_kernel(
    const float* __restrict__ x, const float* __restrict__ w, __half* __restrict__ oh)
{
    int row = blockIdx.x;
    const float4* xr = (const float4*)(x + (size_t)row * D_);
    float ss = 0.f;
    #pragma unroll 4
    for (int i = threadIdx.x; i < D_ / 4; i += 256) {
        float4 v = xr[i];
        ss += v.x * v.x + v.y * v.y + v.z * v.z + v.w * v.w;
    }
    __shared__ float red[8];
    #pragma unroll
    for (int o = 16; o; o >>= 1) ss += __shfl_xor_sync(0xffffffffu, ss, o);
    if ((threadIdx.x & 31) == 0) red[threadIdx.x >> 5] = ss;
    __syncthreads();
    if (threadIdx.x == 0) {
        float t = 0.f;
        #pragma unroll
        for (int i = 0; i < 8; i++) t += red[i];
        red[0] = rsqrtf(t / (float)D_ + 1e-5f);
    }
    __syncthreads();
    float inv = red[0];
    const float4* wr = (const float4*)w;
    for (int i = threadIdx.x; i < D_ / 8; i += 256) {
        float vv[8];
        float4 a = xr[2 * i], b = xr[2 * i + 1];
        float4 wa = wr[2 * i], wb = wr[2 * i + 1];
        vv[0] = a.x * inv * wa.x; vv[1] = a.y * inv * wa.y;
        vv[2] = a.z * inv * wa.z; vv[3] = a.w * inv * wa.w;
        vv[4] = b.x * inv * wb.x; vv[5] = b.y * inv * wb.y;
        vv[6] = b.z * inv * wb.z; vv[7] = b.w * inv * wb.w;
        ((uint4*)(oh + (size_t)row * D_))[i] = cvt8h(vv);
    }
}

// ---------------- RoPE (q and k in place, fp32) ----------------
__global__ void rope_kernel(float* __restrict__ q, float* __restrict__ k)
{
    int s = blockIdx.x;
    int j = threadIdx.x;   // 0..63 pair index
    float inv = (float)exp((double)j * -0.14391156831212787);
    float ang = (float)s * inv;
    float sn, cs;
    sincosf(ang, &sn, &cs);
    #pragma unroll 4
    for (int h = 0; h < H_; h++) {
        size_t base = ((size_t)s * H_ + h) * HD_ + 2 * j;
        float q1 = q[base], q2 = q[base + 1];
        q[base]     = q1 * cs - q2 * sn;
        q[base + 1] = q1 * sn + q2 * cs;
        float k1 = k[base], k2 = k[base + 1];
        k[base]     = k1 * cs - k2 * sn;
        k[base + 1] = k1 * sn + k2 * cs;
    }
}

// ---------------- HMMA flash attention (3-term internal, fp16 O output) ----------------
#define AQH 0
#define AQL 32768
#define AKH 65536
#define AKL 81920
#define AVH 98304
#define AVL 114688
#define ATTN2_SMEM 131072

__global__ __launch_bounds__(256, 1) void attn2_kernel(
    const float* __restrict__ Q, const float* __restrict__ Kg,
    const float* __restrict__ Vg, __half* __restrict__ Oh)
{
    extern __shared__ __align__(1024) char sm2[];
    const uint32_t sb = smem_to_u32(sm2);
    const int tid = threadIdx.x, wid = tid >> 5, lane = tid & 31;
    const int h = blockIdx.y;
    const int bq = gridDim.x - 1 - blockIdx.x;   // long CTAs first
    const int q0 = bq * 128;
    const int mat = lane >> 3, rin = lane & 7;
    const float scale = 0.08838834764831845f;

    // load + scale + split Q tile (128 x 128)
    #pragma unroll
    for (int i = 0; i < 8; i++) {
        int idx = tid + i * 256;
        int row = idx >> 4, cc = idx & 15;
        const float* gp = Q + (size_t)(q0 + row) * D_ + h * HD_ + cc * 8;
        float vv[8];
        float4 a = *(const float4*)gp, b = *(const float4*)(gp + 4);
        vv[0] = a.x * scale; vv[1] = a.y * scale; vv[2] = a.z * scale; vv[3] = a.w * scale;
        vv[4] = b.x * scale; vv[5] = b.y * scale; vv[6] = b.z * scale; vv[7] = b.w * scale;
        uint4 hv, lv;
        cvt8(vv, hv, lv);
        uint32_t off = row * 256 + ((cc ^ (row & 7)) << 4);
        *(uint4*)(sm2 + AQH + off) = hv;
        *(uint4*)(sm2 + AQL + off) = lv;
    }

    float m0 = -1e30f, m1 = -1e30f, l0 = 0.f, l1 = 0.f;
    float oacc[16][4] = {};
    const int g0r = q0 + wid * 16 + (lane >> 2);
    const int g1r = g0r + 8;
    const int nk = q0 / 64 + 2;
    __syncthreads();

    for (int kt = 0; kt < nk; kt++) {
        int k0 = kt * 64;
        // load + split K, V tiles (64 x 128 each)
        #pragma unroll
        for (int i = 0; i < 4; i++) {
            int idx = tid + i * 256;
            int row = idx >> 4, cc = idx & 15;
            uint32_t off = row * 256 + ((cc ^ (row & 7)) << 4);
            const float* kp = Kg + (size_t)(k0 + row) * D_ + h * HD_ + cc * 8;
            float vv[8];
            float4 a = *(const float4*)kp, b = *(const float4*)(kp + 4);
            vv[0] = a.x; vv[1] = a.y; vv[2] = a.z; vv[3] = a.w;
            vv[4] = b.x; vv[5] = b.y; vv[6] = b.z; vv[7] = b.w;
            uint4 hv, lv;
            cvt8(vv, hv, lv);
            *(uint4*)(sm2 + AKH + off) = hv;
            *(uint4*)(sm2 + AKL + off) = lv;
            const float* vp = Vg + (size_t)(k0 + row) * D_ + h * HD_ + cc * 8;
            a = *(const float4*)vp; b = *(const float4*)(vp + 4);
            vv[0] = a.x; vv[1] = a.y; vv[2] = a.z; vv[3] = a.w;
            vv[4] = b.x; vv[5] = b.y; vv[6] = b.z; vv[7] = b.w;
            cvt8(vv, hv, lv);
            *(uint4*)(sm2 + AVH + off) = hv;
            *(uint4*)(sm2 + AVL + off) = lv;
        }
        __syncthreads();

        // S = Q K^T (this warp: 16x64)
        float sacc[8][4] = {};
        #pragma unroll
        for (int kk = 0; kk < 8; kk++) {
            int kk2 = kk << 1;
            int m = wid * 16 + ((mat & 1) << 3) + rin;
            uint32_t ad = sb + AQH + m * 256 + (((kk2 + (mat >> 1)) ^ (m & 7)) << 4);
            uint32_t qa_h[4], qa_l[4];
            LDSM_X4(qa_h[0], qa_h[1], qa_h[2], qa_h[3], ad);
            LDSM_X4(qa_l[0], qa_l[1], qa_l[2], qa_l[3], ad + (AQL - AQH));
            #pragma unroll
            for (int nt = 0; nt < 4; nt++) {
                int n = nt * 16 + ((mat >> 1) << 3) + rin;
                uint32_t bd = sb + AKH + n * 256 + (((kk2 + (mat & 1)) ^ (n & 7)) << 4);
                uint32_t b0, b1, b2, b3, c0, c1, c2, c3;
                LDSM_X4(b0, b1, b2, b3, bd);
                LDSM_X4(c0, c1, c2, c3, bd + (AKL - AKH));
                MMA4(sacc[2 * nt],     qa_h[0], qa_h[1], qa_h[2], qa_h[3], b0, b1);
                MMA4(sacc[2 * nt],     qa_h[0], qa_h[1], qa_h[2], qa_h[3], c0, c1);
                MMA4(sacc[2 * nt],     qa_l[0], qa_l[1], qa_l[2], qa_l[3], b0, b1);
                MMA4(sacc[2 * nt + 1], qa_h[0], qa_h[1], qa_h[2], qa_h[3], b2, b3);
                MMA4(sacc[2 * nt + 1], qa_h[0], qa_h[1], qa_h[2], qa_h[3], c2, c3);
                MMA4(sacc[2 * nt + 1], qa_l[0], qa_l[1], qa_l[2], qa_l[3], b2, b3);
            }
        }

        // causal mask
        if (k0 + 63 > g0r) {
            #pragma unroll
            for (int nt = 0; nt < 8; nt++) {
                int c0 = k0 + nt * 8 + ((lane & 3) << 1);
                if (c0     > g0r) sacc[nt][0] = -1e30f;
                if (c0 + 1 > g0r) sacc[nt][1] = -1e30f;
                if (c0     > g1r) sacc[nt][2] = -1e30f;
                if (c0 + 1 > g1r) sacc[nt][3] = -1e30f;
            }
        }

        // online softmax
        float mx0 = m0, mx1 = m1;
        #pragma unroll
        for (int nt = 0; nt < 8; nt++) {
            mx0 = fmaxf(mx0, fmaxf(sacc[nt][0], sacc[nt][1]));
            mx1 = fmaxf(mx1, fmaxf(sacc[nt][2], sacc[nt][3]));
        }
        mx0 = fmaxf(mx0, __shfl_xor_sync(0xffffffffu, mx0, 1));
        mx0 = fmaxf(mx0, __shfl_xor_sync(0xffffffffu, mx0, 2));
        mx1 = fmaxf(mx1, __shfl_xor_sync(0xffffffffu, mx1, 1));
        mx1 = fmaxf(mx1, __shfl_xor_sync(0xffffffffu, mx1, 2));
        float al0 = __expf(m0 - mx0), al1 = __expf(m1 - mx1);
        m0 = mx0; m1 = mx1;
        float rs0 = 0.f, rs1 = 0.f;
        uint32_t ph0[8], ph1[8], pl0[8], pl1[8];
        #pragma unroll
        for (int nt = 0; nt < 8; nt++) {
            float p0 = __expf(sacc[nt][0] - mx0);
            float p1 = __expf(sacc[nt][1] - mx0);
            float p2 = __expf(sacc[nt][2] - mx1);
            float p3 = __expf(sacc[nt][3] - mx1);
            rs0 += p0 + p1; rs1 += p2 + p3;
            __half h0 = __float2half_rn(p0), h1 = __float2half_rn(p1);
            __half h2 = __float2half_rn(p2), h3 = __float2half_rn(p3);
            ph0[nt] = packh(h0, h1); ph1[nt] = packh(h2, h3);
            pl0[nt] = packh(__float2half_rn(p0 - __half2float(h0)),
                            __float2half_rn(p1 - __half2float(h1)));
            pl1[nt] = packh(__float2half_rn(p2 - __half2float(h2)),
                            __float2half_rn(p3 - __half2float(h3)));
        }
        rs0 += __shfl_xor_sync(0xffffffffu, rs0, 1);
        rs0 += __shfl_xor_sync(0xffffffffu, rs0, 2);
        rs1 += __shfl_xor_sync(0xffffffffu, rs1, 1);
        rs1 += __shfl_xor_sync(0xffffffffu, rs1, 2);
        l0 = l0 * al0 + rs0;
        l1 = l1 * al1 + rs1;
        #pragma unroll
        for (int t = 0; t < 16; t++) {
            oacc[t][0] *= al0; oacc[t][1] *= al0;
            oacc[t][2] *= al1; oacc[t][3] *= al1;
        }

        // O += P @ V
        #pragma unroll
        for (int kk = 0; kk < 4; kk++) {
            uint32_t a0 = ph0[2 * kk], a1 = ph1[2 * kk], a2 = ph0[2 * kk + 1], a3 = ph1[2 * kk + 1];
            uint32_t e0 = pl0[2 * kk], e1 = pl1[2 * kk], e2 = pl0[2 * kk + 1], e3 = pl1[2 * kk + 1];
            #pragma unroll
            for (int ntp = 0; ntp < 8; ntp++) {
                int vrow = kk * 16 + rin + ((mat >> 1) << 3);
                int vch  = 2 * ntp + (mat & 1);
                uint32_t vd = sb + AVH + vrow * 256 + ((vch ^ (vrow & 7)) << 4);
                uint32_t r0, r1, r2, r3, s0, s1, s2, s3;
                LDSM_X4_T(r0, r1, r2, r3, vd);
                LDSM_X4_T(s0, s1, s2, s3, vd + (AVL - AVH));
                MMA4(oacc[2 * ntp],     a0, a1, a2, a3, r0, r2);
                MMA4(oacc[2 * ntp],     a0, a1, a2, a3, s0, s2);
                MMA4(oacc[2 * ntp],     e0, e1, e2, e3, r0, r2);
                MMA4(oacc[2 * ntp + 1], a0, a1, a2, a3, r1, r3);
                MMA4(oacc[2 * ntp + 1], a0, a1, a2, a3, s1, s3);
                MMA4(oacc[2 * ntp + 1], e0, e1, e2, e3, r1, r3);
            }
        }
        __syncthreads();
    }

    // write O (fp16)
    float i0 = 1.f / l0, i1 = 1.f / l1;
    #pragma unroll
    for (int t = 0; t < 16; t++) {
        int col = h * HD_ + t * 8 + ((lane & 3) << 1);
        float v0 = oacc[t][0] * i0, v1 = oacc[t][1] * i0;
        float v2 = oacc[t][2] * i1, v3 = oacc[t][3] * i1;
        *reinterpret_cast<uint32_t*>(Oh + (size_t)g0r * D_ + col) =
            packh(__float2half_rn(v0), __float2half_rn(v1));
        *reinterpret_cast<uint32_t*>(Oh + (size_t)g1r * D_ + col) =
            packh(__float2half_rn(v2), __float2half_rn(v3));
    }
}

// ---------------- SiLU(gate) * up with fused fp16 output ----------------
__global__ void silu_h_kernel(const float* __restrict__ g, const float* __restrict__ u,
                              __half* __restrict__ oh, int n8)
{
    int i = blockIdx.x * blockDim.x + threadIdx.x;
    if (i < n8) {
        float4 g0 = ((const float4*)g)[2 * i], g1 = ((const float4*)g)[2 * i + 1];
        float4 u0 = ((const float4*)u)[2 * i], u1 = ((const float4*)u)[2 * i + 1];
        float vv[8];
        vv[0] = g0.x / (1.f + __expf(-g0.x)) * u0.x;
        vv[1] = g0.y / (1.f + __expf(-g0.y)) * u0.y;
        vv[2] = g0.z / (1.f + __expf(-g0.z)) * u0.z;
        vv[3] = g0.w / (1.f + __expf(-g0.w)) * u0.w;
        vv[4] = g1.x / (1.f + __expf(-g1.x)) * u1.x;
        vv[5] = g1.y / (1.f + __expf(-g1.y)) * u1.y;
        vv[6] = g1.z / (1.f + __expf(-g1.z)) * u1.z;
        vv[7] = g1.w / (1.f + __expf(-g1.w)) * u1.w;
        ((uint4*)oh)[i] = cvt8h(vv);
    }
}

// ---------------- launch ----------------
extern "C" void kernel_launch(void* const* d_in, const int* in_sizes, int n_in,
                              void* d_out, int out_size)
{
    const float* x      = (const float*)d_in[0];
    const float* ln_w   = (const float*)d_in[1];
    const float* ffln_w = (const float*)d_in[2];
    const float* wq     = (const float*)d_in[3];
    const float* wk     = (const float*)d_in[4];
    const float* wv     = (const float*)d_in[5];
    const float* wo     = (const float*)d_in[6];
    const float* wg     = (const float*)d_in[7];
    const float* w1     = (const float*)d_in[8];
    const float* w2     = (const float*)d_in[9];
    float* out = (float*)d_out;

    float *q, *k, *v, *x2, *gate, *up;
    cudaGetSymbolAddress((void**)&q,    g_q);
    cudaGetSymbolAddress((void**)&k,    g_k);
    cudaGetSymbolAddress((void**)&v,    g_v);
    cudaGetSymbolAddress((void**)&x2,   g_x2);
    cudaGetSymbolAddress((void**)&gate, g_gate);
    cudaGetSymbolAddress((void**)&up,   g_up);

    __half *wqt, *wkt, *wvt, *wot, *wgt, *w1t, *w2t, *a_h;
    cudaGetSymbolAddress((void**)&wqt, g_wqt);
    cudaGetSymbolAddress((void**)&wkt, g_wkt);
    cudaGetSymbolAddress((void**)&wvt, g_wvt);
    cudaGetSymbolAddress((void**)&wot, g_wot);
    cudaGetSymbolAddress((void**)&wgt, g_wgt);
    cudaGetSymbolAddress((void**)&w1t, g_w1t);
    cudaGetSymbolAddress((void**)&w2t, g_w2t);
    cudaGetSymbolAddress((void**)&a_h, g_a_h);

    cudaFuncSetAttribute(attn2_kernel, cudaFuncAttributeMaxDynamicSharedMemorySize, ATTN2_SMEM);
    cudaFuncSetAttribute(hgemm<false>, cudaFuncAttributeMaxDynamicSharedMemorySize, HGEMM_SMEM);
    cudaFuncSetAttribute(hgemm<true>,  cudaFuncAttributeMaxDynamicSharedMemorySize, HGEMM_SMEM);

    // weight prep: transpose + fp16 round
    dim3 wt(32, 8);
    wconv_kernel<<<dim3(D_ / 32, D_ / 32), wt>>>(wq, wqt, D_, D_);
    wconv_kernel<<<dim3(D_ / 32, D_ / 32), wt>>>(wk, wkt, D_, D_);
    wconv_kernel<<<dim3(D_ / 32, D_ / 32), wt>>>(wv, wvt, D_, D_);
    wconv_kernel<<<dim3(D_ / 32, D_ / 32), wt>>>(wo, wot, D_, D_);
    wconv_kernel<<<dim3(FF_ / 32, D_ / 32), wt>>>(wg, wgt, D_, FF_);
    wconv_kernel<<<dim3(FF_ / 32, D_ / 32), wt>>>(w1, w1t, D_, FF_);
    wconv_kernel<<<dim3(D_ / 32, FF_ / 32), wt>>>(w2, w2t, FF_, D_);

    // xn = rmsnorm(x) -> a_h
    rmsnorm_h_kernel<<<S_, 256>>>(x, ln_w, a_h);

    // q,k,v projections
    dim3 gdd(S_ / 128, D_ / 128);
    hgemm<false><<<gdd, 256, HGEMM_SMEM>>>(S_, D_, D_, a_h, wqt, nullptr, q);
    hgemm<false><<<gdd, 256, HGEMM_SMEM>>>(S_, D_, D_, a_h, wkt, nullptr, k);
    hgemm<false><<<gdd, 256, HGEMM_SMEM>>>(S_, D_, D_, a_h, wvt, nullptr, v);

    // rope + attention (attention writes fp16 O into a_h)
    rope_kernel<<<S_, 64>>>(q, k);
    attn2_kernel<<<dim3(S_ / 128, H_), 256, ATTN2_SMEM>>>(q, k, v, a_h);

    // x2 = attn @ wo + x
    hgemm<true><<<gdd, 256, HGEMM_SMEM>>>(S_, D_, D_, a_h, wot, x, x2);

    // xn2 = rmsnorm(x2) -> a_h
    rmsnorm_h_kernel<<<S_, 256>>>(x2, ffln_w, a_h);

    // gate/up projections
    dim3 gdf(S_ / 128, FF_ / 128);
    hgemm<false><<<gdf, 256, HGEMM_SMEM>>>(S_, FF_, D_, a_h, wgt, nullptr, gate);
    hgemm<false><<<gdf, 256, HGEMM_SMEM>>>(S_, FF_, D_, a_h, w1t, nullptr, up);

    // h = silu(gate) * up -> a_h
    int n8 = (S_ * FF_) / 8;
    silu_h_kernel<<<(n8 + 255) / 256, 256>>>(gate, up, a_h, n8);

    // out = h @ w2 + x2
    hgemm<true><<<dim3(S_ / 128, D_ / 128), 256, HGEMM_SMEM>>>(S_, D_, FF_, a_h, w2t, x2, out);
}

// round 8
// speedup vs baseline: 3.4774x; 1.1168x over previous
#include <cuda_runtime.h>
#include <cuda_fp16.h>
#include <cstdint>
#include <math.h>

#define S_  2048
#define D_  4096
#define H_  32
#define HD_ 128
#define FF_ 11008

// ---------------- scratch (no allocations allowed) ----------------
__device__ float g_x2 [(size_t)S_ * D_];

__device__ __half g_qh[(size_t)S_ * D_];
__device__ __half g_kh[(size_t)S_ * D_];
__device__ __half g_vh[(size_t)S_ * D_];
__device__ __half g_gh[(size_t)S_ * FF_];
__device__ __half g_uh[(size_t)S_ * FF_];
__device__ __half g_ah[(size_t)S_ * FF_];   // activation input to GEMMs

// transposed fp16 weights, layout [N, K] row-major
__device__ __half g_wqt[(size_t)D_ * D_];
__device__ __half g_wkt[(size_t)D_ * D_];
__device__ __half g_wvt[(size_t)D_ * D_];
__device__ __half g_wot[(size_t)D_ * D_];
__device__ __half g_wgt[(size_t)FF_ * D_];
__device__ __half g_w1t[(size_t)FF_ * D_];
__device__ __half g_w2t[(size_t)D_ * FF_];

// ---------------- asm helpers ----------------
__device__ __forceinline__ uint32_t smem_to_u32(const void* p) {
    uint32_t a;
    asm("{ .reg .u64 t; cvta.to.shared.u64 t, %1; cvt.u32.u64 %0, t; }" : "=r"(a) : "l"(p));
    return a;
}
__device__ __forceinline__ void cp16(uint32_t saddr, const void* gaddr) {
    asm volatile("cp.async.cg.shared.global [%0], [%1], 16;" :: "r"(saddr), "l"(gaddr));
}
#define CP_COMMIT() asm volatile("cp.async.commit_group;" ::: "memory")
#define CP_WAIT(n)  asm volatile("cp.async.wait_group %0;" :: "n"(n) : "memory")

#define LDSM_X4(r0, r1, r2, r3, addr) \
    asm volatile("ldmatrix.sync.aligned.m8n8.x4.shared.b16 {%0,%1,%2,%3}, [%4];" \
        : "=r"(r0), "=r"(r1), "=r"(r2), "=r"(r3) : "r"(addr))
#define LDSM_X4_T(r0, r1, r2, r3, addr) \
    asm volatile("ldmatrix.sync.aligned.m8n8.x4.trans.shared.b16 {%0,%1,%2,%3}, [%4];" \
        : "=r"(r0), "=r"(r1), "=r"(r2), "=r"(r3) : "r"(addr))

#define MMA16816(d, a, b) \
    asm volatile("mma.sync.aligned.m16n8k16.row.col.f32.f16.f16.f32 " \
        "{%0,%1,%2,%3}, {%4,%5,%6,%7}, {%8,%9}, {%0,%1,%2,%3};" \
        : "+f"((d)[0]), "+f"((d)[1]), "+f"((d)[2]), "+f"((d)[3]) \
        : "r"((a)[0]), "r"((a)[1]), "r"((a)[2]), "r"((a)[3]), "r"((b)[0]), "r"((b)[1]))
#define MMA4(d, a0, a1, a2, a3, b0, b1) \
    asm volatile("mma.sync.aligned.m16n8k16.row.col.f32.f16.f16.f32 " \
        "{%0,%1,%2,%3}, {%4,%5,%6,%7}, {%8,%9}, {%0,%1,%2,%3};" \
        : "+f"((d)[0]), "+f"((d)[1]), "+f"((d)[2]), "+f"((d)[3]) \
        : "r"(a0), "r"(a1), "r"(a2), "r"(a3), "r"(b0), "r"(b1))

__device__ __forceinline__ uint32_t packh(__half a, __half b) {
    return ((uint32_t)__half_as_ushort(b) << 16) | __half_as_ushort(a);
}
// 8 floats -> 16B fp16 chunk
__device__ __forceinline__ uint4 cvt8h(const float* v) {
    uint32_t hh[4];
    #pragma unroll
    for (int j = 0; j < 4; j++)
        hh[j] = packh(__float2half_rn(v[2 * j]), __float2half_rn(v[2 * j + 1]));
    return make_uint4(hh[0], hh[1], hh[2], hh[3]);
}

// ---------------- weight transpose + fp16 round (optional scale) ----------------
__global__ __launch_bounds__(256) void wconv_kernel(
    const float* __restrict__ W, __half* __restrict__ Wh, int K, int N, float scale)
{
    __shared__ float t[32][33];
    int n0 = blockIdx.x * 32, k0 = blockIdx.y * 32;
    int tx = threadIdx.x, ty = threadIdx.y; // (32, 8)
    #pragma unroll
    for (int i = 0; i < 4; i++)
        t[ty + 8 * i][tx] = W[(size_t)(k0 + ty + 8 * i) * N + n0 + tx];
    __syncthreads();
    #pragma unroll
    for (int i = 0; i < 4; i++) {
        float v = t[tx][ty + 8 * i] * scale;
        Wh[(size_t)(n0 + ty + 8 * i) * K + k0 + tx] = __float2half_rn(v);
    }
}

// ---------------- HMMA GEMM: plain fp16, CTA 128x128, BK=64, 5-stage ----------------
#define STAGES 5
#define OPBYTES 16384                 // 128 rows x 64 f16 = 16KB
#define STAGE_BYTES (2 * OPBYTES)     // A | B
#define HGEMM_SMEM (STAGES * STAGE_BYTES)

template <bool RESID, bool OUTH>
__global__ __launch_bounds__(256) void hgemm(
    int M, int N, int K,
    const __half* __restrict__ A, const __half* __restrict__ B,
    const float* __restrict__ Rsd, void* __restrict__ Cv)
{
    extern __shared__ __align__(1024) char smem[];
    const int tid  = threadIdx.x;
    const int wid  = tid >> 5;
    const int lane = tid & 31;
    const int m0 = blockIdx.x * 128;
    const int n0 = blockIdx.y * 128;
    const int nk = K >> 6;
    const uint32_t sbase = smem_to_u32(smem);

    const int wm = (wid & 3) * 32;   // warp M offset
    const int wn = (wid >> 2) * 64;  // warp N offset

    const __half* Abase = A + (size_t)m0 * K;
    const __half* Bbase = B + (size_t)n0 * K;

    int lrow[4], lcc[4];
    uint32_t lsoff[4];
    #pragma unroll
    for (int t = 0; t < 4; t++) {
        int c = tid + t * 256;
        lrow[t] = c >> 3;
        lcc[t]  = c & 7;
        lsoff[t] = lrow[t] * 128 + (((lcc[t] ^ (lrow[t] & 7))) << 4);
    }

    #define ISSUE(s, kt) do { \
        uint32_t sb_ = sbase + (s) * STAGE_BYTES; \
        size_t kofs_ = (size_t)(kt) << 6; \
        _Pragma("unroll") \
        for (int t = 0; t < 4; t++) { \
            size_t go_ = (size_t)lrow[t] * K + kofs_ + lcc[t] * 8; \
            uint32_t so_ = sb_ + lsoff[t]; \
            cp16(so_,           Abase + go_); \
            cp16(so_ + OPBYTES, Bbase + go_); \
        } \
    } while (0)

    float acc[2][8][4] = {};

    #pragma unroll
    for (int s = 0; s < STAGES - 1; s++) { ISSUE(s, s); CP_COMMIT(); }

    const int mat = lane >> 3, rin = lane & 7;

    for (int i = 0; i < nk; i++) {
        CP_WAIT(STAGES - 2);
        __syncthreads();
        if (i + STAGES - 1 < nk) { ISSUE((i + STAGES - 1) % STAGES, i + STAGES - 1); }
        CP_COMMIT();

        uint32_t stg = sbase + (i % STAGES) * STAGE_BYTES;
        #pragma unroll
        for (int ks = 0; ks < 4; ks++) {
            int ks2 = ks << 1;
            uint32_t fa[2][4], fb[8][2];
            #pragma unroll
            for (int mt = 0; mt < 2; mt++) {
                int m = wm + mt * 16 + ((mat & 1) << 3) + rin;
                uint32_t ad = stg + m * 128 + (((ks2 + (mat >> 1)) ^ (m & 7)) << 4);
                LDSM_X4(fa[mt][0], fa[mt][1], fa[mt][2], fa[mt][3], ad);
            }
            #pragma unroll
            for (int p = 0; p < 4; p++) {
                int n = wn + p * 16 + ((mat >> 1) << 3) + rin;
                uint32_t bd = stg + OPBYTES + n * 128 + (((ks2 + (mat & 1)) ^ (n & 7)) << 4);
                uint32_t r0, r1, r2, r3;
                LDSM_X4(r0, r1, r2, r3, bd);
                fb[p * 2][0] = r0; fb[p * 2][1] = r1;
                fb[p * 2 + 1][0] = r2; fb[p * 2 + 1][1] = r3;
            }
            #pragma unroll
            for (int mt = 0; mt < 2; mt++)
                #pragma unroll
                for (int nt = 0; nt < 8; nt++)
                    MMA16816(acc[mt][nt], fa[mt], fb[nt]);
        }
        __syncthreads();
    }
    #undef ISSUE

    int qr = lane >> 2, qc = (lane & 3) << 1;
    #pragma unroll
    for (int mt = 0; mt < 2; mt++) {
        #pragma unroll
        for (int nt = 0; nt < 8; nt++) {
            int r0 = m0 + wm + mt * 16 + qr;
            int cc = n0 + wn + nt * 8 + qc;
            if (OUTH) {
                __half* Ch = (__half*)Cv;
                *reinterpret_cast<uint32_t*>(Ch + (size_t)r0 * N + cc) =
                    packh(__float2half_rn(acc[mt][nt][0]), __float2half_rn(acc[mt][nt][1]));
                *reinterpret_cast<uint32_t*>(Ch + (size_t)(r0 + 8) * N + cc) =
                    packh(__float2half_rn(acc[mt][nt][2]), __float2half_rn(acc[mt][nt][3]));
            } else {
                float* C = (float*)Cv;
                float2 v0 = make_float2(acc[mt][nt][0], acc[mt][nt][1]);
                float2 v1 = make_float2(acc[mt][nt][2], acc[mt][nt][3]);
                if (RESID) {
                    float2 a = *(const float2*)(Rsd + (size_t)r0 * N + cc);
                    float2 b = *(const float2*)(Rsd + (size_t)(r0 + 8) * N + cc);
                    v0.x += a.x; v0.y += a.y; v1.x += b.x; v1.y += b.y;
                }
                *(float2*)(C + (size_t)r0 * N + cc)       = v0;
                *(float2*)(C + (size_t)(r0 + 8) * N + cc) = v1;
            }
        }
    }
}

// ---------------- RMSNorm with fused fp16 output ----------------
__global__ __launch_bounds__(256) void rmsnorm_h_kernel(
    const float* __restrict__ x, const float* __restrict__ w, __half* __restrict__ oh)
{
    int row = blockIdx.x;
    const float4* xr = (const float4*)(x + (size_t)row * D_);
    float ss = 0.f;
    #pragma unroll 4
    for (int i = threadIdx.x; i < D_ / 4; i += 256) {
        float4 v = xr[i];
        ss += v.x * v.x + v.y * v.y + v.z * v.z + v.w * v.w;
    }
    __shared__ float red[8];
    #pragma unroll
    for (int o = 16; o; o >>= 1) ss += __shfl_xor_sync(0xffffffffu, ss, o);
    if ((threadIdx.x & 31) == 0) red[threadIdx.x >> 5] = ss;
    __syncthreads();
    if (threadIdx.x == 0) {
        float t = 0.f;
        #pragma unroll
        for (int i = 0; i < 8; i++) t += red[i];
        red[0] = rsqrtf(t / (float)D_ + 1e-5f);
    }
    __syncthreads();
    float inv = red[0];
    const float4* wr = (const float4*)w;
    for (int i = threadIdx.x; i < D_ / 8; i += 256) {
        float vv[8];
        float4 a = xr[2 * i], b = xr[2 * i + 1];
        float4 wa = wr[2 * i], wb = wr[2 * i + 1];
        vv[0] = a.x * inv * wa.x; vv[1] = a.y * inv * wa.y;
        vv[2] = a.z * inv * wa.z; vv[3] = a.w * inv * wa.w;
        vv[4] = b.x * inv * wb.x; vv[5] = b.y * inv * wb.y;
        vv[6] = b.z * inv * wb.z; vv[7] = b.w * inv * wb.w;
        ((uint4*)(oh + (size_t)row * D_))[i] = cvt8h(vv);
    }
}

// ---------------- RoPE (q and k in place, fp16) ----------------
__global__ void rope_h_kernel(__half* __restrict__ q, __half* __restrict__ k)
{
    int s = blockIdx.x;
    int j = threadIdx.x;   // 0..63 pair index
    float inv = (float)exp((double)j * -0.14391156831212787);
    float ang = (float)s * inv;
    float sn, cs;
    sincosf(ang, &sn, &cs);
    #pragma unroll 4
    for (int h = 0; h < H_; h++) {
        size_t base = ((size_t)s * H_ + h) * HD_ + 2 * j;
        uint32_t* qp = reinterpret_cast<uint32_t*>(q + base);
        uint32_t* kp = reinterpret_cast<uint32_t*>(k + base);
        __half2 qv = *reinterpret_cast<__half2*>(qp);
        __half2 kv = *reinterpret_cast<__half2*>(kp);
        float q1 = __low2float(qv), q2 = __high2float(qv);
        float k1 = __low2float(kv), k2 = __high2float(kv);
        *qp = packh(__float2half_rn(q1 * cs - q2 * sn), __float2half_rn(q1 * sn + q2 * cs));
        *kp = packh(__float2half_rn(k1 * cs - k2 * sn), __float2half_rn(k1 * sn + k2 * cs));
    }
}

// ---------------- HMMA flash attention v3: fp16 in/out, 1-term, double-buffered KV ----------------
#define ATQ 0
#define ATK(b) (32768 + (b) * 32768)
#define ATV(b) (ATK(b) + 16384)
#define ATTN3_SMEM 98304

__global__ __launch_bounds__(256, 1) void attn3_kernel(
    const __half* __restrict__ Q, const __half* __restrict__ Kg,
    const __half* __restrict__ Vg, __half* __restrict__ Oh)
{
    extern __shared__ __align__(1024) char sm2[];
    const uint32_t sb = smem_to_u32(sm2);
    const int tid = threadIdx.x, wid = tid >> 5, lane = tid & 31;
    const int h = blockIdx.y;
    const int bq = gridDim.x - 1 - blockIdx.x;   // long CTAs first
    const int q0 = bq * 128;
    const int mat = lane >> 3, rin = lane & 7;

    // Q tile (128 x 128 f16 = 32KB), pure cp.async copy (scale folded into wq)
    #pragma unroll
    for (int i = 0; i < 8; i++) {
        int idx = tid + i * 256;
        int row = idx >> 4, cc = idx & 15;
        cp16(sb + ATQ + row * 256 + ((cc ^ (row & 7)) << 4),
             Q + (size_t)(q0 + row) * D_ + h * HD_ + cc * 8);
    }
    CP_COMMIT();

    #define ISSUEKV(b, kt) do { \
        int k0_ = (kt) * 64; \
        _Pragma("unroll") \
        for (int i_ = 0; i_ < 4; i_++) { \
            int idx_ = tid + i_ * 256; \
            int row_ = idx_ >> 4, cc_ = idx_ & 15; \
            uint32_t off_ = row_ * 256 + ((cc_ ^ (row_ & 7)) << 4); \
            cp16(sb + ATK(b) + off_, Kg + (size_t)(k0_ + row_) * D_ + h * HD_ + cc_ * 8); \
            cp16(sb + ATV(b) + off_, Vg + (size_t)(k0_ + row_) * D_ + h * HD_ + cc_ * 8); \
        } \
    } while (0)

    const int nk = q0 / 64 + 2;
    ISSUEKV(0, 0); CP_COMMIT();

    float m0 = -1e30f, m1 = -1e30f, l0 = 0.f, l1 = 0.f;
    float oacc[16][4] = {};
    const int g0r = q0 + wid * 16 + (lane >> 2);
    const int g1r = g0r + 8;

    for (int kt = 0; kt < nk; kt++) {
        if (kt + 1 < nk) { ISSUEKV((kt + 1) & 1, kt + 1); CP_COMMIT(); CP_WAIT(1); }
        else            { CP_WAIT(0); }
        __syncthreads();
        int k0 = kt * 64;
        int buf = kt & 1;

        // S = Q K^T (this warp: 16x64)
        float sacc[8][4] = {};
        #pragma unroll
        for (int kk = 0; kk < 8; kk++) {
            int kk2 = kk << 1;
            int m = wid * 16 + ((mat & 1) << 3) + rin;
            uint32_t ad = sb + ATQ + m * 256 + (((kk2 + (mat >> 1)) ^ (m & 7)) << 4);
            uint32_t qa[4];
            LDSM_X4(qa[0], qa[1], qa[2], qa[3], ad);
            #pragma unroll
            for (int nt = 0; nt < 4; nt++) {
                int n = nt * 16 + ((mat >> 1) << 3) + rin;
                uint32_t bd = sb + ATK(buf) + n * 256 + (((kk2 + (mat & 1)) ^ (n & 7)) << 4);
                uint32_t b0, b1, b2, b3;
                LDSM_X4(b0, b1, b2, b3, bd);
                MMA4(sacc[2 * nt],     qa[0], qa[1], qa[2], qa[3], b0, b1);
                MMA4(sacc[2 * nt + 1], qa[0], qa[1], qa[2], qa[3], b2, b3);
            }
        }

        // causal mask
        if (k0 + 63 > g0r) {
            #pragma unroll
            for (int nt = 0; nt < 8; nt++) {
                int c0 = k0 + nt * 8 + ((lane & 3) << 1);
                if (c0     > g0r) sacc[nt][0] = -1e30f;
                if (c0 + 1 > g0r) sacc[nt][1] = -1e30f;
                if (c0     > g1r) sacc[nt][2] = -1e30f;
                if (c0 + 1 > g1r) sacc[nt][3] = -1e30f;
            }
        }

        // online softmax
        float mx0 = m0, mx1 = m1;
        #pragma unroll
        for (int nt = 0; nt < 8; nt++) {
            mx0 = fmaxf(mx0, fmaxf(sacc[nt][0], sacc[nt][1]));
            mx1 = fmaxf(mx1, fmaxf(sacc[nt][2], sacc[nt][3]));
        }
        mx0 = fmaxf(mx0, __shfl_xor_sync(0xffffffffu, mx0, 1));
        mx0 = fmaxf(mx0, __shfl_xor_sync(0xffffffffu, mx0, 2));
        mx1 = fmaxf(mx1, __shfl_xor_sync(0xffffffffu, mx1, 1));
        mx1 = fmaxf(mx1, __shfl_xor_sync(0xffffffffu, mx1, 2));
        float al0 = __expf(m0 - mx0), al1 = __expf(m1 - mx1);
        m0 = mx0; m1 = mx1;
        float rs0 = 0.f, rs1 = 0.f;
        uint32_t ph0[8], ph1[8];
        #pragma unroll
        for (int nt = 0; nt < 8; nt++) {
            float p0 = __expf(sacc[nt][0] - mx0);
            float p1 = __expf(sacc[nt][1] - mx0);
            float p2 = __expf(sacc[nt][2] - mx1);
            float p3 = __expf(sacc[nt][3] - mx1);
            rs0 += p0 + p1; rs1 += p2 + p3;
            ph0[nt] = packh(__float2half_rn(p0), __float2half_rn(p1));
            ph1[nt] = packh(__float2half_rn(p2), __float2half_rn(p3));
        }
        rs0 += __shfl_xor_sync(0xffffffffu, rs0, 1);
        rs0 += __shfl_xor_sync(0xffffffffu, rs0, 2);
        rs1 += __shfl_xor_sync(0xffffffffu, rs1, 1);
        rs1 += __shfl_xor_sync(0xffffffffu, rs1, 2);
        l0 = l0 * al0 + rs0;
        l1 = l1 * al1 + rs1;
        #pragma unroll
        for (int t = 0; t < 16; t++) {
            oacc[t][0] *= al0; oacc[t][1] *= al0;
            oacc[t][2] *= al1; oacc[t][3] *= al1;
        }

        // O += P @ V
        #pragma unroll
        for (int kk = 0; kk < 4; kk++) {
            uint32_t a0 = ph0[2 * kk], a1 = ph1[2 * kk], a2 = ph0[2 * kk + 1], a3 = ph1[2 * kk + 1];
            #pragma unroll
            for (int ntp = 0; ntp < 8; ntp++) {
                int vrow = kk * 16 + rin + ((mat >> 1) << 3);
                int vch  = 2 * ntp + (mat & 1);
                uint32_t vd = sb + ATV(buf) + vrow * 256 + ((vch ^ (vrow & 7)) << 4);
                uint32_t r0, r1, r2, r3;
                LDSM_X4_T(r0, r1, r2, r3, vd);
                MMA4(oacc[2 * ntp],     a0, a1, a2, a3, r0, r2);
                MMA4(oacc[2 * ntp + 1], a0, a1, a2, a3, r1, r3);
            }
        }
        __syncthreads();
    }
    #undef ISSUEKV

    // write O (fp16)
    float i0 = 1.f / l0, i1 = 1.f / l1;
    #pragma unroll
    for (int t = 0; t < 16; t++) {
        int col = h * HD_ + t * 8 + ((lane & 3) << 1);
        *reinterpret_cast<uint32_t*>(Oh + (size_t)g0r * D_ + col) =
            packh(__float2half_rn(oacc[t][0] * i0), __float2half_rn(oacc[t][1] * i0));
        *reinterpret_cast<uint32_t*>(Oh + (size_t)g1r * D_ + col) =
            packh(__float2half_rn(oacc[t][2] * i1), __float2half_rn(oacc[t][3] * i1));
    }
}

// ---------------- SiLU(gate) * up (fp16 in, fp16 out) ----------------
__global__ void silu_h_kernel(const __half* __restrict__ g, const __half* __restrict__ u,
                              __half* __restrict__ oh, int n8)
{
    int i = blockIdx.x * blockDim.x + threadIdx.x;
    if (i < n8) {
        uint4 gv = ((const uint4*)g)[i];
        uint4 uv = ((const uint4*)u)[i];
        const uint32_t* gp = &gv.x;
        const uint32_t* up = &uv.x;
        float vv[8];
        #pragma unroll
        for (int j = 0; j < 4; j++) {
            float2 gf = __half22float2(*reinterpret_cast<const __half2*>(&gp[j]));
            float2 uf = __half22float2(*reinterpret_cast<const __half2*>(&up[j]));
            vv[2 * j]     = gf.x / (1.f + __expf(-gf.x)) * uf.x;
            vv[2 * j + 1] = gf.y / (1.f + __expf(-gf.y)) * uf.y;
        }
        ((uint4*)oh)[i] = cvt8h(vv);
    }
}

// ---------------- launch ----------------
extern "C" void kernel_launch(void* const* d_in, const int* in_sizes, int n_in,
                              void* d_out, int out_size)
{
    const float* x      = (const float*)d_in[0];
    const float* ln_w   = (const float*)d_in[1];
    const float* ffln_w = (const float*)d_in[2];
    const float* wq     = (const float*)d_in[3];
    const float* wk     = (const float*)d_in[4];
    const float* wv     = (const float*)d_in[5];
    const float* wo     = (const float*)d_in[6];
    const float* wg     = (const float*)d_in[7];
    const float* w1     = (const float*)d_in[8];
    const float* w2     = (const float*)d_in[9];
    float* out = (float*)d_out;

    float* x2;
    cudaGetSymbolAddress((void**)&x2, g_x2);

    __half *qh, *kh, *vh, *gh, *uh, *ah;
    cudaGetSymbolAddress((void**)&qh, g_qh);
    cudaGetSymbolAddress((void**)&kh, g_kh);
    cudaGetSymbolAddress((void**)&vh, g_vh);
    cudaGetSymbolAddress((void**)&gh, g_gh);
    cudaGetSymbolAddress((void**)&uh, g_uh);
    cudaGetSymbolAddress((void**)&ah, g_ah);

    __half *wqt, *wkt, *wvt, *wot, *wgt, *w1t, *w2t;
    cudaGetSymbolAddress((void**)&wqt, g_wqt);
    cudaGetSymbolAddress((void**)&wkt, g_wkt);
    cudaGetSymbolAddress((void**)&wvt, g_wvt);
    cudaGetSymbolAddress((void**)&wot, g_wot);
    cudaGetSymbolAddress((void**)&wgt, g_wgt);
    cudaGetSymbolAddress((void**)&w1t, g_w1t);
    cudaGetSymbolAddress((void**)&w2t, g_w2t);

    cudaFuncSetAttribute(attn3_kernel, cudaFuncAttributeMaxDynamicSharedMemorySize, ATTN3_SMEM);
    cudaFuncSetAttribute(hgemm<false, true>,  cudaFuncAttributeMaxDynamicSharedMemorySize, HGEMM_SMEM);
    cudaFuncSetAttribute(hgemm<false, false>, cudaFuncAttributeMaxDynamicSharedMemorySize, HGEMM_SMEM);
    cudaFuncSetAttribute(hgemm<true,  false>, cudaFuncAttributeMaxDynamicSharedMemorySize, HGEMM_SMEM);

    // weight prep: transpose + fp16 round (wq carries 1/sqrt(HD))
    const float qscale = 0.08838834764831845f;
    dim3 wt(32, 8);
    wconv_kernel<<<dim3(D_ / 32, D_ / 32), wt>>>(wq, wqt, D_, D_, qscale);
    wconv_kernel<<<dim3(D_ / 32, D_ / 32), wt>>>(wk, wkt, D_, D_, 1.f);
    wconv_kernel<<<dim3(D_ / 32, D_ / 32), wt>>>(wv, wvt, D_, D_, 1.f);
    wconv_kernel<<<dim3(D_ / 32, D_ / 32), wt>>>(wo, wot, D_, D_, 1.f);
    wconv_kernel<<<dim3(FF_ / 32, D_ / 32), wt>>>(wg, wgt, D_, FF_, 1.f);
    wconv_kernel<<<dim3(FF_ / 32, D_ / 32), wt>>>(w1, w1t, D_, FF_, 1.f);
    wconv_kernel<<<dim3(D_ / 32, FF_ / 32), wt>>>(w2, w2t, FF_, D_, 1.f);

    // xn = rmsnorm(x) -> ah
    rmsnorm_h_kernel<<<S_, 256>>>(x, ln_w, ah);

    // q,k,v projections (fp16 out)
    dim3 gdd(S_ / 128, D_ / 128);
    hgemm<false, true><<<gdd, 256, HGEMM_SMEM>>>(S_, D_, D_, ah, wqt, nullptr, qh);
    hgemm<false, true><<<gdd, 256, HGEMM_SMEM>>>(S_, D_, D_, ah, wkt, nullptr, kh);
    hgemm<false, true><<<gdd, 256, HGEMM_SMEM>>>(S_, D_, D_, ah, wvt, nullptr, vh);

    // rope + attention (fp16 end-to-end; O -> ah)
    rope_h_kernel<<<S_, 64>>>(qh, kh);
    attn3_kernel<<<dim3(S_ / 128, H_), 256, ATTN3_SMEM>>>(qh, kh, vh, ah);

    // x2 = attn @ wo + x   (fp32 out)
    hgemm<true, false><<<gdd, 256, HGEMM_SMEM>>>(S_, D_, D_, ah, wot, x, x2);

    // xn2 = rmsnorm(x2) -> ah
    rmsnorm_h_kernel<<<S_, 256>>>(x2, ffln_w, ah);

    // gate/up projections (fp16 out)
    dim3 gdf(S_ / 128, FF_ / 128);
    hgemm<false, true><<<gdf, 256, HGEMM_SMEM>>>(S_, FF_, D_, ah, wgt, nullptr, gh);
    hgemm<false, true><<<gdf, 256, HGEMM_SMEM>>>(S_, FF_, D_, ah, w1t, nullptr, uh);

    // h = silu(gate) * up -> ah
    int n8 = (S_ * FF_) / 8;
    silu_h_kernel<<<(n8 + 255) / 256, 256>>>(gh, uh, ah, n8);

    // out = h @ w2 + x2  (fp32 out)
    hgemm<true, false><<<dim3(S_ / 128, D_ / 128), 256, HGEMM_SMEM>>>(S_, D_, FF_, ah, w2t, x2, out);
}